// round 2
// baseline (speedup 1.0000x reference)
#include <cuda_runtime.h>
#include <math.h>

// Problem constants
#define SQ   2048   // sequence length
#define HID  768    // hidden
#define BB   2      // batch
#define NH   12     // heads
#define DH   64     // head dim
#define RR   5      // structural deps
#define BN   24     // BB*NH

// ---------------- device scratch (allocation-free) ----------------
// qext: slot 0 = q, slots 1..5 = q @ bili[r]   [slot][bn][s][d]
__device__ float g_qext[(size_t)6 * BN * SQ * DH];     //  75.5 MB
__device__ float g_k   [(size_t)BN * SQ * DH];         //  12.6 MB
__device__ float g_v   [(size_t)BN * SQ * DH];         //  12.6 MB
__device__ float g_scores[(size_t)BN * SQ * SQ];       // 402.7 MB

// =================================================================
// Kernel 1: QKV projection.  out = X @ W^T + b, written in head layout.
// grid (12 otiles, 64 mtiles, 3 {q,k,v}), block 256, 4x4 microtile.
// =================================================================
__global__ __launch_bounds__(256) void proj_kernel(
    const float* __restrict__ X,
    const float* __restrict__ Wq, const float* __restrict__ Wk,
    const float* __restrict__ Wv,
    const float* __restrict__ bq, const float* __restrict__ bk,
    const float* __restrict__ bv)
{
    const int otile = blockIdx.x, mtile = blockIdx.y, z = blockIdx.z;
    const float* W    = (z == 0) ? Wq : (z == 1) ? Wk : Wv;
    const float* bias = (z == 0) ? bq : (z == 1) ? bk : bv;
    float* outp       = (z == 0) ? g_qext : (z == 1) ? g_k : g_v;

    __shared__ float Xs[16][68];   // [k][m]
    __shared__ float Ws[16][68];   // [k][o]

    const int t  = threadIdx.x;
    const int tx = t & 15, ty = t >> 4;
    const int lrow = t >> 2;          // 0..63
    const int lk4  = (t & 3) << 2;    // 0,4,8,12

    const float* Xbase = X + (size_t)(mtile * 64 + lrow) * HID;
    const float* Wbase = W + (size_t)(otile * 64 + lrow) * HID;

    float acc[4][4] = {};

    for (int k0 = 0; k0 < HID; k0 += 16) {
        float4 xv = *(const float4*)(Xbase + k0 + lk4);
        float4 wv = *(const float4*)(Wbase + k0 + lk4);
        __syncthreads();
        Xs[lk4 + 0][lrow] = xv.x; Xs[lk4 + 1][lrow] = xv.y;
        Xs[lk4 + 2][lrow] = xv.z; Xs[lk4 + 3][lrow] = xv.w;
        Ws[lk4 + 0][lrow] = wv.x; Ws[lk4 + 1][lrow] = wv.y;
        Ws[lk4 + 2][lrow] = wv.z; Ws[lk4 + 3][lrow] = wv.w;
        __syncthreads();
#pragma unroll
        for (int kk = 0; kk < 16; kk++) {
            float4 a = *(const float4*)&Xs[kk][ty << 2];
            float4 b = *(const float4*)&Ws[kk][tx << 2];
            acc[0][0] += a.x * b.x; acc[0][1] += a.x * b.y;
            acc[0][2] += a.x * b.z; acc[0][3] += a.x * b.w;
            acc[1][0] += a.y * b.x; acc[1][1] += a.y * b.y;
            acc[1][2] += a.y * b.z; acc[1][3] += a.y * b.w;
            acc[2][0] += a.z * b.x; acc[2][1] += a.z * b.y;
            acc[2][2] += a.z * b.z; acc[2][3] += a.z * b.w;
            acc[3][0] += a.w * b.x; acc[3][1] += a.w * b.y;
            acc[3][2] += a.w * b.z; acc[3][3] += a.w * b.w;
        }
    }

    // epilogue: n == otile (64-aligned tiles), d = tx*4+jj
    const int n = otile;
#pragma unroll
    for (int ii = 0; ii < 4; ii++) {
        int m = mtile * 64 + (ty << 2) + ii;
        int b = m / SQ, s = m % SQ;
        float* dst = outp + ((size_t)(b * NH + n) * SQ + s) * DH + (tx << 2);
        float4 o;
        o.x = acc[ii][0] + bias[otile * 64 + (tx << 2) + 0];
        o.y = acc[ii][1] + bias[otile * 64 + (tx << 2) + 1];
        o.z = acc[ii][2] + bias[otile * 64 + (tx << 2) + 2];
        o.w = acc[ii][3] + bias[otile * 64 + (tx << 2) + 3];
        *(float4*)dst = o;
    }
}

// =================================================================
// Kernel 2: q'_r = q @ bili[r,n].  grid (32 itiles, 24 bn, 5 r).
// =================================================================
__global__ __launch_bounds__(256) void qb_kernel(const float* __restrict__ bili)
{
    const int itile = blockIdx.x, bn = blockIdx.y, r = blockIdx.z;
    const int n = bn % NH;

    __shared__ float qs[64][68];    // [p][i]
    __shared__ float bs[64 * 64];   // [p][q] direct

    const int t  = threadIdx.x;
    const int tx = t & 15, ty = t >> 4;

    // load q tile transposed (64x64, 4 float4 per thread)
#pragma unroll
    for (int c = 0; c < 4; c++) {
        int id  = t + 256 * c;
        int row = id >> 4;
        int p4  = (id & 15) << 2;
        float4 v = *(const float4*)&g_qext[((size_t)bn * SQ + itile * 64 + row) * DH + p4];
        qs[p4 + 0][row] = v.x; qs[p4 + 1][row] = v.y;
        qs[p4 + 2][row] = v.z; qs[p4 + 3][row] = v.w;
    }
    // load bili[r][n] direct
    const float* bb = bili + ((size_t)r * NH + n) * DH * DH;
#pragma unroll
    for (int c = 0; c < 4; c++) {
        int id = t + 256 * c;
        *(float4*)&bs[id << 2] = *(const float4*)(bb + (id << 2));
    }
    __syncthreads();

    float acc[4][4] = {};
#pragma unroll 16
    for (int p = 0; p < 64; p++) {
        float4 a = *(const float4*)&qs[p][ty << 2];
        float4 b = *(const float4*)&bs[p * 64 + (tx << 2)];
        acc[0][0] += a.x * b.x; acc[0][1] += a.x * b.y;
        acc[0][2] += a.x * b.z; acc[0][3] += a.x * b.w;
        acc[1][0] += a.y * b.x; acc[1][1] += a.y * b.y;
        acc[1][2] += a.y * b.z; acc[1][3] += a.y * b.w;
        acc[2][0] += a.z * b.x; acc[2][1] += a.z * b.y;
        acc[2][2] += a.z * b.z; acc[2][3] += a.z * b.w;
        acc[3][0] += a.w * b.x; acc[3][1] += a.w * b.y;
        acc[3][2] += a.w * b.z; acc[3][3] += a.w * b.w;
    }

#pragma unroll
    for (int ii = 0; ii < 4; ii++) {
        int i = itile * 64 + (ty << 2) + ii;
        float4 o = make_float4(acc[ii][0], acc[ii][1], acc[ii][2], acc[ii][3]);
        *(float4*)&g_qext[(((size_t)(1 + r) * BN + bn) * SQ + i) * DH + (tx << 2)] = o;
    }
}

// =================================================================
// Kernel 3: fused score = q.k + sum_r adj_r*(q'_r.k + ab_r), scaled + mask.
// grid (32 jtiles, 32 itiles, 24 bn), block 256, 4x4 microtile.
// =================================================================
__global__ __launch_bounds__(256) void score_kernel(
    const float* __restrict__ adj,   // [R][B][1][S][S]
    const float* __restrict__ absb,  // [R][N]
    const float* __restrict__ mask)  // [B][1][1][S]
{
    const int jt = blockIdx.x, it = blockIdx.y, bn = blockIdx.z;
    const int b = bn / NH, n = bn % NH;

    __shared__ float ks[64][68];   // [d][j]
    __shared__ float qs[64][68];   // [d][i]

    const int t  = threadIdx.x;
    const int tx = t & 15, ty = t >> 4;

    // load k tile transposed (once)
#pragma unroll
    for (int c = 0; c < 4; c++) {
        int id  = t + 256 * c;
        int row = id >> 4;
        int p4  = (id & 15) << 2;
        float4 v = *(const float4*)&g_k[((size_t)bn * SQ + jt * 64 + row) * DH + p4];
        ks[p4 + 0][row] = v.x; ks[p4 + 1][row] = v.y;
        ks[p4 + 2][row] = v.z; ks[p4 + 3][row] = v.w;
    }

    float acc[4][4];

    for (int slot = 0; slot < 6; slot++) {
        __syncthreads();   // previous pass done before overwriting qs (also orders ks on slot 0)
#pragma unroll
        for (int c = 0; c < 4; c++) {
            int id  = t + 256 * c;
            int row = id >> 4;
            int p4  = (id & 15) << 2;
            float4 v = *(const float4*)&g_qext[(((size_t)slot * BN + bn) * SQ + it * 64 + row) * DH + p4];
            qs[p4 + 0][row] = v.x; qs[p4 + 1][row] = v.y;
            qs[p4 + 2][row] = v.z; qs[p4 + 3][row] = v.w;
        }
        __syncthreads();

        float tmp[4][4] = {};
#pragma unroll 16
        for (int p = 0; p < 64; p++) {
            float4 a = *(const float4*)&qs[p][ty << 2];
            float4 kb = *(const float4*)&ks[p][tx << 2];
            tmp[0][0] += a.x * kb.x; tmp[0][1] += a.x * kb.y;
            tmp[0][2] += a.x * kb.z; tmp[0][3] += a.x * kb.w;
            tmp[1][0] += a.y * kb.x; tmp[1][1] += a.y * kb.y;
            tmp[1][2] += a.y * kb.z; tmp[1][3] += a.y * kb.w;
            tmp[2][0] += a.z * kb.x; tmp[2][1] += a.z * kb.y;
            tmp[2][2] += a.z * kb.z; tmp[2][3] += a.z * kb.w;
            tmp[3][0] += a.w * kb.x; tmp[3][1] += a.w * kb.y;
            tmp[3][2] += a.w * kb.z; tmp[3][3] += a.w * kb.w;
        }

        if (slot == 0) {
#pragma unroll
            for (int ii = 0; ii < 4; ii++)
#pragma unroll
                for (int jj = 0; jj < 4; jj++) acc[ii][jj] = tmp[ii][jj];
        } else {
            const int r = slot - 1;
            const float ab = absb[r * NH + n];
#pragma unroll
            for (int ii = 0; ii < 4; ii++) {
                int ig = it * 64 + (ty << 2) + ii;
                float4 av = *(const float4*)&adj[(((size_t)r * BB + b) * SQ + ig) * SQ + jt * 64 + (tx << 2)];
                acc[ii][0] += av.x * (tmp[ii][0] + ab);
                acc[ii][1] += av.y * (tmp[ii][1] + ab);
                acc[ii][2] += av.z * (tmp[ii][2] + ab);
                acc[ii][3] += av.w * (tmp[ii][3] + ab);
            }
        }
    }

    // scale (1/sqrt(64)) + additive mask, write scores
    const float scale = 0.125f;
    float4 mk = *(const float4*)&mask[b * SQ + jt * 64 + (tx << 2)];
#pragma unroll
    for (int ii = 0; ii < 4; ii++) {
        int ig = it * 64 + (ty << 2) + ii;
        float4 o;
        o.x = acc[ii][0] * scale + mk.x;
        o.y = acc[ii][1] * scale + mk.y;
        o.z = acc[ii][2] * scale + mk.z;
        o.w = acc[ii][3] * scale + mk.w;
        *(float4*)&g_scores[((size_t)bn * SQ + ig) * SQ + jt * 64 + (tx << 2)] = o;
    }
}

// =================================================================
// Kernel 4: row softmax in place.  grid = BN*S blocks, 256 threads.
// =================================================================
__global__ __launch_bounds__(256) void softmax_kernel()
{
    const size_t row = blockIdx.x;
    float* p = g_scores + row * (size_t)SQ;
    const int t = threadIdx.x;

    float v[8];
    float m = -1e30f;
#pragma unroll
    for (int c = 0; c < 8; c++) {
        v[c] = p[t + 256 * c];
        m = fmaxf(m, v[c]);
    }
#pragma unroll
    for (int off = 16; off > 0; off >>= 1)
        m = fmaxf(m, __shfl_xor_sync(0xffffffffu, m, off));

    __shared__ float redm[8];
    __shared__ float reds[8];
    __shared__ float bcast[2];
    const int warp = t >> 5, lane = t & 31;
    if (lane == 0) redm[warp] = m;
    __syncthreads();
    if (t == 0) {
        float mm = redm[0];
#pragma unroll
        for (int w = 1; w < 8; w++) mm = fmaxf(mm, redm[w]);
        bcast[0] = mm;
    }
    __syncthreads();
    m = bcast[0];

    float s = 0.f;
#pragma unroll
    for (int c = 0; c < 8; c++) {
        v[c] = __expf(v[c] - m);
        s += v[c];
    }
#pragma unroll
    for (int off = 16; off > 0; off >>= 1)
        s += __shfl_xor_sync(0xffffffffu, s, off);
    if (lane == 0) reds[warp] = s;
    __syncthreads();
    if (t == 0) {
        float ss = 0.f;
#pragma unroll
        for (int w = 0; w < 8; w++) ss += reds[w];
        bcast[1] = 1.0f / ss;
    }
    __syncthreads();
    const float inv = bcast[1];
#pragma unroll
    for (int c = 0; c < 8; c++) p[t + 256 * c] = v[c] * inv;
}

// =================================================================
// Kernel 5: ctx = P @ V, write output in [b, s, n*64+d] layout.
// grid (32 itiles, 24 bn), block 256.
// =================================================================
__global__ __launch_bounds__(256) void ctx_kernel(float* __restrict__ out)
{
    const int it = blockIdx.x, bn = blockIdx.y;
    const int b = bn / NH, n = bn % NH;

    __shared__ float ps[64][68];   // [j][i]
    __shared__ float vs[64 * 64];  // [j][d]

    const int t  = threadIdx.x;
    const int tx = t & 15, ty = t >> 4;

    float acc[4][4] = {};

    for (int jt = 0; jt < 32; jt++) {
        __syncthreads();
#pragma unroll
        for (int c = 0; c < 4; c++) {
            int id  = t + 256 * c;
            int row = id >> 4;
            int q4  = (id & 15) << 2;
            float4 pv = *(const float4*)&g_scores[((size_t)bn * SQ + it * 64 + row) * SQ + jt * 64 + q4];
            ps[q4 + 0][row] = pv.x; ps[q4 + 1][row] = pv.y;
            ps[q4 + 2][row] = pv.z; ps[q4 + 3][row] = pv.w;
            float4 vv = *(const float4*)&g_v[((size_t)bn * SQ + jt * 64 + row) * DH + q4];
            *(float4*)&vs[row * 64 + q4] = vv;
        }
        __syncthreads();

#pragma unroll 16
        for (int j = 0; j < 64; j++) {
            float4 a  = *(const float4*)&ps[j][ty << 2];
            float4 bv = *(const float4*)&vs[j * 64 + (tx << 2)];
            acc[0][0] += a.x * bv.x; acc[0][1] += a.x * bv.y;
            acc[0][2] += a.x * bv.z; acc[0][3] += a.x * bv.w;
            acc[1][0] += a.y * bv.x; acc[1][1] += a.y * bv.y;
            acc[1][2] += a.y * bv.z; acc[1][3] += a.y * bv.w;
            acc[2][0] += a.z * bv.x; acc[2][1] += a.z * bv.y;
            acc[2][2] += a.z * bv.z; acc[2][3] += a.z * bv.w;
            acc[3][0] += a.w * bv.x; acc[3][1] += a.w * bv.y;
            acc[3][2] += a.w * bv.z; acc[3][3] += a.w * bv.w;
        }
    }

#pragma unroll
    for (int ii = 0; ii < 4; ii++) {
        int i = it * 64 + (ty << 2) + ii;
        float4 o = make_float4(acc[ii][0], acc[ii][1], acc[ii][2], acc[ii][3]);
        *(float4*)&out[((size_t)b * SQ + i) * HID + n * 64 + (tx << 2)] = o;
    }
}

// =================================================================
extern "C" void kernel_launch(void* const* d_in, const int* in_sizes, int n_in,
                              void* d_out, int out_size)
{
    const float* hidden = (const float*)d_in[0];
    const float* mask   = (const float*)d_in[1];
    const float* adj    = (const float*)d_in[2];
    const float* Wq     = (const float*)d_in[3];
    const float* bq     = (const float*)d_in[4];
    const float* Wk     = (const float*)d_in[5];
    const float* bk     = (const float*)d_in[6];
    const float* Wv     = (const float*)d_in[7];
    const float* bv     = (const float*)d_in[8];
    const float* bili   = (const float*)d_in[9];
    const float* absb   = (const float*)d_in[10];
    float* out = (float*)d_out;
    (void)in_sizes; (void)n_in; (void)out_size;

    proj_kernel<<<dim3(HID / 64, (BB * SQ) / 64, 3), 256>>>(hidden, Wq, Wk, Wv, bq, bk, bv);
    qb_kernel<<<dim3(SQ / 64, BN, RR), 256>>>(bili);
    score_kernel<<<dim3(SQ / 64, SQ / 64, BN), 256>>>(adj, absb, mask);
    softmax_kernel<<<BN * SQ, 256>>>();
    ctx_kernel<<<dim3(SQ / 64, BN), 256>>>(out);
}

// round 4
// speedup vs baseline: 1.6992x; 1.6992x over previous
#include <cuda_runtime.h>
#include <cuda_bf16.h>
#include <cstdint>
#include <math.h>

#define SQ   2048
#define HID  768
#define BB   2
#define NH   12
#define DH   64
#define RR   5
#define BN   24

// ---------------- device scratch ----------------
__device__ float g_qext[(size_t)6 * BN * SQ * DH];
__device__ float g_k   [(size_t)BN * SQ * DH];
__device__ float g_v   [(size_t)BN * SQ * DH];
__device__ float g_scores[(size_t)BN * SQ * SQ];
__device__ __nv_bfloat16 g_qh[(size_t)6 * BN * SQ * DH];
__device__ __nv_bfloat16 g_ql[(size_t)6 * BN * SQ * DH];
__device__ __nv_bfloat16 g_kh[(size_t)BN * SQ * DH];
__device__ __nv_bfloat16 g_kl[(size_t)BN * SQ * DH];
__device__ unsigned g_adjbits[(size_t)RR * BB * (SQ / 32) * SQ];

// ================= helpers =================
__device__ __forceinline__ uint32_t smem_to_u32(const void* p) {
    uint32_t a;
    asm("{ .reg .u64 t; cvta.to.shared.u64 t, %1; cvt.u32.u64 %0, t; }" : "=r"(a) : "l"(p));
    return a;
}
__device__ __forceinline__ unsigned pack2(__nv_bfloat16 a, __nv_bfloat16 b) {
    __nv_bfloat162 t; t.x = a; t.y = b;
    return *reinterpret_cast<unsigned*>(&t);
}
__device__ __forceinline__ void ldsm_x4(uint32_t* r, uint32_t addr) {
    asm volatile("ldmatrix.sync.aligned.m8n8.x4.shared.b16 {%0,%1,%2,%3}, [%4];"
        : "=r"(r[0]), "=r"(r[1]), "=r"(r[2]), "=r"(r[3]) : "r"(addr));
}
__device__ __forceinline__ void ldsm_x2(uint32_t* r, uint32_t addr) {
    asm volatile("ldmatrix.sync.aligned.m8n8.x2.shared.b16 {%0,%1}, [%2];"
        : "=r"(r[0]), "=r"(r[1]) : "r"(addr));
}
__device__ __forceinline__ void mma16816(float* d, const uint32_t* a, const uint32_t* b) {
    asm volatile(
        "mma.sync.aligned.m16n8k16.row.col.f32.bf16.bf16.f32 "
        "{%0,%1,%2,%3}, {%4,%5,%6,%7}, {%8,%9}, {%0,%1,%2,%3};"
        : "+f"(d[0]), "+f"(d[1]), "+f"(d[2]), "+f"(d[3])
        : "r"(a[0]), "r"(a[1]), "r"(a[2]), "r"(a[3]), "r"(b[0]), "r"(b[1]));
}

// ============ Kernel 1: QKV projection (fp32) ============
__global__ __launch_bounds__(256) void proj_kernel(
    const float* __restrict__ X,
    const float* __restrict__ Wq, const float* __restrict__ Wk, const float* __restrict__ Wv,
    const float* __restrict__ bq, const float* __restrict__ bk, const float* __restrict__ bv)
{
    const int otile = blockIdx.x, mtile = blockIdx.y, z = blockIdx.z;
    const float* W    = (z == 0) ? Wq : (z == 1) ? Wk : Wv;
    const float* bias = (z == 0) ? bq : (z == 1) ? bk : bv;
    float* outp       = (z == 0) ? g_qext : (z == 1) ? g_k : g_v;
    __shared__ float Xs[16][68], Ws[16][68];
    const int t = threadIdx.x, tx = t & 15, ty = t >> 4;
    const int lrow = t >> 2, lk4 = (t & 3) << 2;
    const float* Xb = X + (size_t)(mtile * 64 + lrow) * HID;
    const float* Wb = W + (size_t)(otile * 64 + lrow) * HID;
    float acc[4][4] = {};
    for (int k0 = 0; k0 < HID; k0 += 16) {
        float4 xv = *(const float4*)(Xb + k0 + lk4);
        float4 wv = *(const float4*)(Wb + k0 + lk4);
        __syncthreads();
        Xs[lk4 + 0][lrow] = xv.x; Xs[lk4 + 1][lrow] = xv.y; Xs[lk4 + 2][lrow] = xv.z; Xs[lk4 + 3][lrow] = xv.w;
        Ws[lk4 + 0][lrow] = wv.x; Ws[lk4 + 1][lrow] = wv.y; Ws[lk4 + 2][lrow] = wv.z; Ws[lk4 + 3][lrow] = wv.w;
        __syncthreads();
#pragma unroll
        for (int kk = 0; kk < 16; kk++) {
            float4 a = *(const float4*)&Xs[kk][ty << 2];
            float4 b = *(const float4*)&Ws[kk][tx << 2];
            acc[0][0] += a.x * b.x; acc[0][1] += a.x * b.y; acc[0][2] += a.x * b.z; acc[0][3] += a.x * b.w;
            acc[1][0] += a.y * b.x; acc[1][1] += a.y * b.y; acc[1][2] += a.y * b.z; acc[1][3] += a.y * b.w;
            acc[2][0] += a.z * b.x; acc[2][1] += a.z * b.y; acc[2][2] += a.z * b.z; acc[2][3] += a.z * b.w;
            acc[3][0] += a.w * b.x; acc[3][1] += a.w * b.y; acc[3][2] += a.w * b.z; acc[3][3] += a.w * b.w;
        }
    }
    const int n = otile;
#pragma unroll
    for (int ii = 0; ii < 4; ii++) {
        int m = mtile * 64 + (ty << 2) + ii;
        int b = m / SQ, s = m % SQ;
        float* dst = outp + ((size_t)(b * NH + n) * SQ + s) * DH + (tx << 2);
        float4 o;
        o.x = acc[ii][0] + bias[otile * 64 + (tx << 2) + 0];
        o.y = acc[ii][1] + bias[otile * 64 + (tx << 2) + 1];
        o.z = acc[ii][2] + bias[otile * 64 + (tx << 2) + 2];
        o.w = acc[ii][3] + bias[otile * 64 + (tx << 2) + 3];
        *(float4*)dst = o;
    }
}

// ============ Kernel 2: q'_r = q @ bili[r,n] (fp32) ============
__global__ __launch_bounds__(256) void qb_kernel(const float* __restrict__ bili)
{
    const int itile = blockIdx.x, bn = blockIdx.y, r = blockIdx.z;
    const int n = bn % NH;
    __shared__ float qs[64][68];
    __shared__ float bs[64 * 64];
    const int t = threadIdx.x, tx = t & 15, ty = t >> 4;
#pragma unroll
    for (int c = 0; c < 4; c++) {
        int id = t + 256 * c, row = id >> 4, p4 = (id & 15) << 2;
        float4 v = *(const float4*)&g_qext[((size_t)bn * SQ + itile * 64 + row) * DH + p4];
        qs[p4 + 0][row] = v.x; qs[p4 + 1][row] = v.y; qs[p4 + 2][row] = v.z; qs[p4 + 3][row] = v.w;
    }
    const float* bb = bili + ((size_t)r * NH + n) * DH * DH;
#pragma unroll
    for (int c = 0; c < 4; c++) {
        int id = t + 256 * c;
        *(float4*)&bs[id << 2] = *(const float4*)(bb + (id << 2));
    }
    __syncthreads();
    float acc[4][4] = {};
#pragma unroll 16
    for (int p = 0; p < 64; p++) {
        float4 a = *(const float4*)&qs[p][ty << 2];
        float4 b = *(const float4*)&bs[p * 64 + (tx << 2)];
        acc[0][0] += a.x * b.x; acc[0][1] += a.x * b.y; acc[0][2] += a.x * b.z; acc[0][3] += a.x * b.w;
        acc[1][0] += a.y * b.x; acc[1][1] += a.y * b.y; acc[1][2] += a.y * b.z; acc[1][3] += a.y * b.w;
        acc[2][0] += a.z * b.x; acc[2][1] += a.z * b.y; acc[2][2] += a.z * b.z; acc[2][3] += a.z * b.w;
        acc[3][0] += a.w * b.x; acc[3][1] += a.w * b.y; acc[3][2] += a.w * b.z; acc[3][3] += a.w * b.w;
    }
#pragma unroll
    for (int ii = 0; ii < 4; ii++) {
        int i = itile * 64 + (ty << 2) + ii;
        float4 o = make_float4(acc[ii][0], acc[ii][1], acc[ii][2], acc[ii][3]);
        *(float4*)&g_qext[(((size_t)(1 + r) * BN + bn) * SQ + i) * DH + (tx << 2)] = o;
    }
}

// ============ Kernel 3: fp32 -> bf16 hi/lo ============
__global__ __launch_bounds__(256) void conv_kernel(int which, int n4)
{
    int c = blockIdx.x * 256 + threadIdx.x;
    if (c >= n4) return;
    const float4* src = which ? (const float4*)g_k : (const float4*)g_qext;
    uint2* hi = which ? (uint2*)g_kh : (uint2*)g_qh;
    uint2* lo = which ? (uint2*)g_kl : (uint2*)g_ql;
    float4 v = src[c];
    __nv_bfloat16 hx = __float2bfloat16(v.x), hy = __float2bfloat16(v.y);
    __nv_bfloat16 hz = __float2bfloat16(v.z), hw = __float2bfloat16(v.w);
    uint2 h; h.x = pack2(hx, hy); h.y = pack2(hz, hw);
    uint2 l;
    l.x = pack2(__float2bfloat16(v.x - __bfloat162float(hx)), __float2bfloat16(v.y - __bfloat162float(hy)));
    l.y = pack2(__float2bfloat16(v.z - __bfloat162float(hz)), __float2bfloat16(v.w - __bfloat162float(hw)));
    hi[c] = h; lo[c] = l;
}

// ============ Kernel 4: pack adj -> bitmask [r][b][jword][i] ============
__global__ __launch_bounds__(256) void pack_kernel(const float* __restrict__ adj)
{
    const int jw = blockIdx.x, b = blockIdx.y, r = blockIdx.z;
#pragma unroll
    for (int ii = 0; ii < 8; ii++) {
        int i = threadIdx.x + 256 * ii;
        const float* src = adj + (((size_t)(r * BB + b)) * SQ + i) * SQ + jw * 32;
        unsigned bits = 0;
#pragma unroll
        for (int e8 = 0; e8 < 8; e8++) {
            float4 v = *(const float4*)(src + e8 * 4);
            bits |= (unsigned)(v.x != 0.f) << (e8 * 4 + 0);
            bits |= (unsigned)(v.y != 0.f) << (e8 * 4 + 1);
            bits |= (unsigned)(v.z != 0.f) << (e8 * 4 + 2);
            bits |= (unsigned)(v.w != 0.f) << (e8 * 4 + 3);
        }
        g_adjbits[((size_t)(r * BB + b) * 64 + jw) * SQ + i] = bits;
    }
}

// ============ Kernel 5: score via mma.sync (HMMA bf16, hi/lo split) ============
// grid (NH, SQ/64, BB), block 256 (8 warps).
// SMEM: 12 q tiles (slot x {hi,lo}) 8KB each, then k tile {hi,lo} 8KB each.
#define QT(slot, half) (((slot) * 2 + (half)) * 8192)
#define KT(half)       (98304 + (half) * 8192)
#define SC_SMEM        114688
#define SWZ8(row, ch)  (((row) * 128) + ((((ch) ^ ((row) & 7))) << 4))

__global__ __launch_bounds__(256) void score_mma_kernel(
    const float* __restrict__ absb, const float* __restrict__ mask)
{
    extern __shared__ char smem[];
    const uint32_t sbase = smem_to_u32(smem);
    const int n = blockIdx.x, it = blockIdx.y, b = blockIdx.z;
    const int bn = b * NH + n;
    const int i0 = it * 64;
    const int tid = threadIdx.x, wid = tid >> 5, lane = tid & 31;
    const int m0 = (wid & 3) * 16;          // warp row offset within 64-row tile
    const int n0 = (wid >> 2) * 32;         // warp col offset within 64-col k tile

    // ---- load 12 q tiles, swizzled ----
#pragma unroll
    for (int c = 0; c < 24; c++) {
        int idx = tid + 256 * c;
        int tile = idx >> 9;                // 512 uint4 per tile
        int rem = idx & 511;
        int row = rem >> 3, ch = rem & 7;
        int slot = tile >> 1, half = tile & 1;
        const __nv_bfloat16* src = (half ? g_ql : g_qh) +
            (((size_t)slot * BN + bn) * SQ + i0 + row) * DH + ch * 8;
        *(uint4*)(smem + QT(0, 0) + tile * 8192 + SWZ8(row, ch)) = *(const uint4*)src;
    }

    float ab[RR];
#pragma unroll
    for (int r = 0; r < RR; r++) ab[r] = absb[r * NH + n];

    // per-lane A address pieces: rows fixed per lane
    const int rowA = m0 + (lane & 15);
    const int selA = lane >> 4;             // 0: k-chunk lo16B, 1: hi16B
    // B address pieces
    const int rowB = n0 + (lane & 7);       // replicated for lanes 16-31 (ignored)
    const int selB = (lane >> 3) & 1;

    const int row1 = i0 + m0 + (lane >> 2);
    const int row2 = row1 + 8;

    for (int jt = 0; jt < 32; jt++) {
        __syncthreads();
        // ---- load k tile hi/lo ----
#pragma unroll
        for (int c = 0; c < 4; c++) {
            int idx = tid + 256 * c;
            int half = idx >> 9;
            int rem = idx & 511;
            int row = rem >> 3, ch = rem & 7;
            const __nv_bfloat16* src = (half ? g_kl : g_kh) +
                ((size_t)bn * SQ + jt * 64 + row) * DH + ch * 8;
            *(uint4*)(smem + KT(half) + SWZ8(row, ch)) = *(const uint4*)src;
        }
        __syncthreads();

        // ---- hoist B fragments: [half][ks][nf][2] ----
        uint32_t Bf[2][4][4][2];
#pragma unroll
        for (int h = 0; h < 2; h++)
#pragma unroll
            for (int ks = 0; ks < 4; ks++)
#pragma unroll
                for (int nf = 0; nf < 4; nf++) {
                    int r = rowB + nf * 8;
                    uint32_t addr = sbase + KT(h) + SWZ8(r, ks * 2 + selB);
                    ldsm_x2(Bf[h][ks][nf], addr);
                }

        // adjacency words for this jt
        const int jw = jt * 2 + (wid >> 2);
        unsigned aw1[RR], aw2[RR];
#pragma unroll
        for (int r = 0; r < RR; r++) {
            aw1[r] = g_adjbits[((size_t)(r * BB + b) * 64 + jw) * SQ + row1];
            aw2[r] = g_adjbits[((size_t)(r * BB + b) * 64 + jw) * SQ + row2];
        }

        float fin[16];
#pragma unroll
        for (int s = 0; s < 6; s++) {
            float tmp[16] = {};
#pragma unroll
            for (int ks = 0; ks < 4; ks++) {
                uint32_t Ah[4], Al[4];
                ldsm_x4(Ah, sbase + QT(s, 0) + SWZ8(rowA, ks * 2 + selA));
                ldsm_x4(Al, sbase + QT(s, 1) + SWZ8(rowA, ks * 2 + selA));
#pragma unroll
                for (int nf = 0; nf < 4; nf++) {
                    mma16816(tmp + nf * 4, Ah, Bf[0][ks][nf]);   // hi*hi
                    mma16816(tmp + nf * 4, Ah, Bf[1][ks][nf]);   // hi*lo
                    mma16816(tmp + nf * 4, Al, Bf[0][ks][nf]);   // lo*hi
                }
            }
            if (s == 0) {
#pragma unroll
                for (int e = 0; e < 16; e++) fin[e] = tmp[e];
            } else {
                const int r = s - 1;
                const float abr = ab[r];
#pragma unroll
                for (int nf = 0; nf < 4; nf++) {
                    int sh = nf * 8 + 2 * (lane & 3);
                    if ((aw1[r] >> sh) & 1)       fin[nf * 4 + 0] += tmp[nf * 4 + 0] + abr;
                    if ((aw1[r] >> (sh + 1)) & 1) fin[nf * 4 + 1] += tmp[nf * 4 + 1] + abr;
                    if ((aw2[r] >> sh) & 1)       fin[nf * 4 + 2] += tmp[nf * 4 + 2] + abr;
                    if ((aw2[r] >> (sh + 1)) & 1) fin[nf * 4 + 3] += tmp[nf * 4 + 3] + abr;
                }
            }
        }

        // ---- scale + mask + store ----
#pragma unroll
        for (int nf = 0; nf < 4; nf++) {
            int j = jt * 64 + n0 + nf * 8 + 2 * (lane & 3);
            float2 mk = __ldg((const float2*)&mask[b * SQ + j]);
            float2 o1, o2;
            o1.x = fin[nf * 4 + 0] * 0.125f + mk.x;
            o1.y = fin[nf * 4 + 1] * 0.125f + mk.y;
            o2.x = fin[nf * 4 + 2] * 0.125f + mk.x;
            o2.y = fin[nf * 4 + 3] * 0.125f + mk.y;
            *(float2*)&g_scores[((size_t)bn * SQ + row1) * SQ + j] = o1;
            *(float2*)&g_scores[((size_t)bn * SQ + row2) * SQ + j] = o2;
        }
    }
}

// ============ Kernel 6: softmax ============
__global__ __launch_bounds__(256) void softmax_kernel()
{
    const size_t row = blockIdx.x;
    float* p = g_scores + row * (size_t)SQ;
    const int t = threadIdx.x;
    float v[8];
    float m = -1e30f;
#pragma unroll
    for (int c = 0; c < 8; c++) { v[c] = p[t + 256 * c]; m = fmaxf(m, v[c]); }
#pragma unroll
    for (int off = 16; off > 0; off >>= 1) m = fmaxf(m, __shfl_xor_sync(0xffffffffu, m, off));
    __shared__ float redm[8], reds[8], bcast[2];
    const int warp = t >> 5, lane = t & 31;
    if (lane == 0) redm[warp] = m;
    __syncthreads();
    if (t == 0) {
        float mm = redm[0];
#pragma unroll
        for (int w = 1; w < 8; w++) mm = fmaxf(mm, redm[w]);
        bcast[0] = mm;
    }
    __syncthreads();
    m = bcast[0];
    float s = 0.f;
#pragma unroll
    for (int c = 0; c < 8; c++) { v[c] = __expf(v[c] - m); s += v[c]; }
#pragma unroll
    for (int off = 16; off > 0; off >>= 1) s += __shfl_xor_sync(0xffffffffu, s, off);
    if (lane == 0) reds[warp] = s;
    __syncthreads();
    if (t == 0) {
        float ss = 0.f;
#pragma unroll
        for (int w = 0; w < 8; w++) ss += reds[w];
        bcast[1] = 1.0f / ss;
    }
    __syncthreads();
    const float inv = bcast[1];
#pragma unroll
    for (int c = 0; c < 8; c++) p[t + 256 * c] = v[c] * inv;
}

// ============ Kernel 7: ctx = P @ V (fp32) ============
__global__ __launch_bounds__(256) void ctx_kernel(float* __restrict__ out)
{
    const int it = blockIdx.x, bn = blockIdx.y;
    const int b = bn / NH, n = bn % NH;
    __shared__ float ps[64][68];
    __shared__ float vs[64 * 64];
    const int t = threadIdx.x, tx = t & 15, ty = t >> 4;
    float acc[4][4] = {};
    for (int jt = 0; jt < 32; jt++) {
        __syncthreads();
#pragma unroll
        for (int c = 0; c < 4; c++) {
            int id = t + 256 * c, row = id >> 4, q4 = (id & 15) << 2;
            float4 pv = *(const float4*)&g_scores[((size_t)bn * SQ + it * 64 + row) * SQ + jt * 64 + q4];
            ps[q4 + 0][row] = pv.x; ps[q4 + 1][row] = pv.y; ps[q4 + 2][row] = pv.z; ps[q4 + 3][row] = pv.w;
            float4 vv = *(const float4*)&g_v[((size_t)bn * SQ + jt * 64 + row) * DH + q4];
            *(float4*)&vs[row * 64 + q4] = vv;
        }
        __syncthreads();
#pragma unroll 16
        for (int j = 0; j < 64; j++) {
            float4 a  = *(const float4*)&ps[j][ty << 2];
            float4 bv = *(const float4*)&vs[j * 64 + (tx << 2)];
            acc[0][0] += a.x * bv.x; acc[0][1] += a.x * bv.y; acc[0][2] += a.x * bv.z; acc[0][3] += a.x * bv.w;
            acc[1][0] += a.y * bv.x; acc[1][1] += a.y * bv.y; acc[1][2] += a.y * bv.z; acc[1][3] += a.y * bv.w;
            acc[2][0] += a.z * bv.x; acc[2][1] += a.z * bv.y; acc[2][2] += a.z * bv.z; acc[2][3] += a.z * bv.w;
            acc[3][0] += a.w * bv.x; acc[3][1] += a.w * bv.y; acc[3][2] += a.w * bv.z; acc[3][3] += a.w * bv.w;
        }
    }
#pragma unroll
    for (int ii = 0; ii < 4; ii++) {
        int i = it * 64 + (ty << 2) + ii;
        float4 o = make_float4(acc[ii][0], acc[ii][1], acc[ii][2], acc[ii][3]);
        *(float4*)&out[((size_t)b * SQ + i) * HID + n * 64 + (tx << 2)] = o;
    }
}

// =================================================================
extern "C" void kernel_launch(void* const* d_in, const int* in_sizes, int n_in,
                              void* d_out, int out_size)
{
    const float* hidden = (const float*)d_in[0];
    const float* mask   = (const float*)d_in[1];
    const float* adj    = (const float*)d_in[2];
    const float* Wq     = (const float*)d_in[3];
    const float* bq     = (const float*)d_in[4];
    const float* Wk     = (const float*)d_in[5];
    const float* bk     = (const float*)d_in[6];
    const float* Wv     = (const float*)d_in[7];
    const float* bv     = (const float*)d_in[8];
    const float* bili   = (const float*)d_in[9];
    const float* absb   = (const float*)d_in[10];
    float* out = (float*)d_out;
    (void)in_sizes; (void)n_in; (void)out_size;

    cudaFuncSetAttribute(score_mma_kernel, cudaFuncAttributeMaxDynamicSharedMemorySize, SC_SMEM);

    proj_kernel<<<dim3(HID / 64, (BB * SQ) / 64, 3), 256>>>(hidden, Wq, Wk, Wv, bq, bk, bv);
    qb_kernel<<<dim3(SQ / 64, BN, RR), 256>>>(bili);
    conv_kernel<<<(6 * BN * SQ * DH / 4 + 255) / 256, 256>>>(0, 6 * BN * SQ * DH / 4);
    conv_kernel<<<(BN * SQ * DH / 4 + 255) / 256, 256>>>(1, BN * SQ * DH / 4);
    pack_kernel<<<dim3(SQ / 32, BB, RR), 256>>>(adj);
    score_mma_kernel<<<dim3(NH, SQ / 64, BB), 256, SC_SMEM>>>(absb, mask);
    softmax_kernel<<<BN * SQ, 256>>>();
    ctx_kernel<<<dim3(SQ / 64, BN), 256>>>(out);
}

// round 5
// speedup vs baseline: 2.0701x; 1.2182x over previous
#include <cuda_runtime.h>
#include <cuda_bf16.h>
#include <cstdint>
#include <math.h>

#define SQ   2048
#define HID  768
#define BB   2
#define NH   12
#define DH   64
#define RR   5
#define BN   24

// ---------------- device scratch ----------------
__device__ float g_qext[(size_t)6 * BN * SQ * DH];
__device__ float g_k   [(size_t)BN * SQ * DH];
__device__ float g_v   [(size_t)BN * SQ * DH];
__device__ __nv_bfloat16 g_qh[(size_t)6 * BN * SQ * DH];
__device__ __nv_bfloat16 g_ql[(size_t)6 * BN * SQ * DH];
__device__ __nv_bfloat16 g_kh[(size_t)BN * SQ * DH];
__device__ __nv_bfloat16 g_kl[(size_t)BN * SQ * DH];
__device__ __nv_bfloat16 g_vth[(size_t)BN * DH * SQ];   // V^T [bn][d][s] hi
__device__ __nv_bfloat16 g_vtl[(size_t)BN * DH * SQ];   // V^T [bn][d][s] lo
__device__ unsigned g_adjbits[(size_t)RR * BB * (SQ / 32) * SQ];

// ================= helpers =================
__device__ __forceinline__ uint32_t smem_to_u32(const void* p) {
    uint32_t a;
    asm("{ .reg .u64 t; cvta.to.shared.u64 t, %1; cvt.u32.u64 %0, t; }" : "=r"(a) : "l"(p));
    return a;
}
__device__ __forceinline__ unsigned pack2(__nv_bfloat16 a, __nv_bfloat16 b) {
    __nv_bfloat162 t; t.x = a; t.y = b;
    return *reinterpret_cast<unsigned*>(&t);
}
__device__ __forceinline__ void ldsm_x4(uint32_t* r, uint32_t addr) {
    asm volatile("ldmatrix.sync.aligned.m8n8.x4.shared.b16 {%0,%1,%2,%3}, [%4];"
        : "=r"(r[0]), "=r"(r[1]), "=r"(r[2]), "=r"(r[3]) : "r"(addr));
}
__device__ __forceinline__ void ldsm_x2(uint32_t* r, uint32_t addr) {
    asm volatile("ldmatrix.sync.aligned.m8n8.x2.shared.b16 {%0,%1}, [%2];"
        : "=r"(r[0]), "=r"(r[1]) : "r"(addr));
}
__device__ __forceinline__ void mma16816(float* d, const uint32_t* a, const uint32_t* b) {
    asm volatile(
        "mma.sync.aligned.m16n8k16.row.col.f32.bf16.bf16.f32 "
        "{%0,%1,%2,%3}, {%4,%5,%6,%7}, {%8,%9}, {%0,%1,%2,%3};"
        : "+f"(d[0]), "+f"(d[1]), "+f"(d[2]), "+f"(d[3])
        : "r"(a[0]), "r"(a[1]), "r"(a[2]), "r"(a[3]), "r"(b[0]), "r"(b[1]));
}
__device__ __forceinline__ unsigned split_hi(float x, float y, float& lx, float& ly) {
    __nv_bfloat16 hx = __float2bfloat16(x), hy = __float2bfloat16(y);
    lx = x - __bfloat162float(hx);
    ly = y - __bfloat162float(hy);
    return pack2(hx, hy);
}

// ============ Kernel 1: QKV projection (fp32) ============
__global__ __launch_bounds__(256) void proj_kernel(
    const float* __restrict__ X,
    const float* __restrict__ Wq, const float* __restrict__ Wk, const float* __restrict__ Wv,
    const float* __restrict__ bq, const float* __restrict__ bk, const float* __restrict__ bv)
{
    const int otile = blockIdx.x, mtile = blockIdx.y, z = blockIdx.z;
    const float* W    = (z == 0) ? Wq : (z == 1) ? Wk : Wv;
    const float* bias = (z == 0) ? bq : (z == 1) ? bk : bv;
    float* outp       = (z == 0) ? g_qext : (z == 1) ? g_k : g_v;
    __shared__ float Xs[16][68], Ws[16][68];
    const int t = threadIdx.x, tx = t & 15, ty = t >> 4;
    const int lrow = t >> 2, lk4 = (t & 3) << 2;
    const float* Xb = X + (size_t)(mtile * 64 + lrow) * HID;
    const float* Wb = W + (size_t)(otile * 64 + lrow) * HID;
    float acc[4][4] = {};
    for (int k0 = 0; k0 < HID; k0 += 16) {
        float4 xv = *(const float4*)(Xb + k0 + lk4);
        float4 wv = *(const float4*)(Wb + k0 + lk4);
        __syncthreads();
        Xs[lk4 + 0][lrow] = xv.x; Xs[lk4 + 1][lrow] = xv.y; Xs[lk4 + 2][lrow] = xv.z; Xs[lk4 + 3][lrow] = xv.w;
        Ws[lk4 + 0][lrow] = wv.x; Ws[lk4 + 1][lrow] = wv.y; Ws[lk4 + 2][lrow] = wv.z; Ws[lk4 + 3][lrow] = wv.w;
        __syncthreads();
#pragma unroll
        for (int kk = 0; kk < 16; kk++) {
            float4 a = *(const float4*)&Xs[kk][ty << 2];
            float4 b = *(const float4*)&Ws[kk][tx << 2];
            acc[0][0] += a.x * b.x; acc[0][1] += a.x * b.y; acc[0][2] += a.x * b.z; acc[0][3] += a.x * b.w;
            acc[1][0] += a.y * b.x; acc[1][1] += a.y * b.y; acc[1][2] += a.y * b.z; acc[1][3] += a.y * b.w;
            acc[2][0] += a.z * b.x; acc[2][1] += a.z * b.y; acc[2][2] += a.z * b.z; acc[2][3] += a.z * b.w;
            acc[3][0] += a.w * b.x; acc[3][1] += a.w * b.y; acc[3][2] += a.w * b.z; acc[3][3] += a.w * b.w;
        }
    }
    const int n = otile;
#pragma unroll
    for (int ii = 0; ii < 4; ii++) {
        int m = mtile * 64 + (ty << 2) + ii;
        int b = m / SQ, s = m % SQ;
        float* dst = outp + ((size_t)(b * NH + n) * SQ + s) * DH + (tx << 2);
        float4 o;
        o.x = acc[ii][0] + bias[otile * 64 + (tx << 2) + 0];
        o.y = acc[ii][1] + bias[otile * 64 + (tx << 2) + 1];
        o.z = acc[ii][2] + bias[otile * 64 + (tx << 2) + 2];
        o.w = acc[ii][3] + bias[otile * 64 + (tx << 2) + 3];
        *(float4*)dst = o;
    }
}

// ============ Kernel 2: q'_r = q @ bili[r,n] (fp32) ============
__global__ __launch_bounds__(256) void qb_kernel(const float* __restrict__ bili)
{
    const int itile = blockIdx.x, bn = blockIdx.y, r = blockIdx.z;
    const int n = bn % NH;
    __shared__ float qs[64][68];
    __shared__ float bs[64 * 64];
    const int t = threadIdx.x, tx = t & 15, ty = t >> 4;
#pragma unroll
    for (int c = 0; c < 4; c++) {
        int id = t + 256 * c, row = id >> 4, p4 = (id & 15) << 2;
        float4 v = *(const float4*)&g_qext[((size_t)bn * SQ + itile * 64 + row) * DH + p4];
        qs[p4 + 0][row] = v.x; qs[p4 + 1][row] = v.y; qs[p4 + 2][row] = v.z; qs[p4 + 3][row] = v.w;
    }
    const float* bb = bili + ((size_t)r * NH + n) * DH * DH;
#pragma unroll
    for (int c = 0; c < 4; c++) {
        int id = t + 256 * c;
        *(float4*)&bs[id << 2] = *(const float4*)(bb + (id << 2));
    }
    __syncthreads();
    float acc[4][4] = {};
#pragma unroll 16
    for (int p = 0; p < 64; p++) {
        float4 a = *(const float4*)&qs[p][ty << 2];
        float4 b = *(const float4*)&bs[p * 64 + (tx << 2)];
        acc[0][0] += a.x * b.x; acc[0][1] += a.x * b.y; acc[0][2] += a.x * b.z; acc[0][3] += a.x * b.w;
        acc[1][0] += a.y * b.x; acc[1][1] += a.y * b.y; acc[1][2] += a.y * b.z; acc[1][3] += a.y * b.w;
        acc[2][0] += a.z * b.x; acc[2][1] += a.z * b.y; acc[2][2] += a.z * b.z; acc[2][3] += a.z * b.w;
        acc[3][0] += a.w * b.x; acc[3][1] += a.w * b.y; acc[3][2] += a.w * b.z; acc[3][3] += a.w * b.w;
    }
#pragma unroll
    for (int ii = 0; ii < 4; ii++) {
        int i = itile * 64 + (ty << 2) + ii;
        float4 o = make_float4(acc[ii][0], acc[ii][1], acc[ii][2], acc[ii][3]);
        *(float4*)&g_qext[(((size_t)(1 + r) * BN + bn) * SQ + i) * DH + (tx << 2)] = o;
    }
}

// ============ Kernel 3: fp32 -> bf16 hi/lo (q or k) ============
__global__ __launch_bounds__(256) void conv_kernel(int which, int n4)
{
    int c = blockIdx.x * 256 + threadIdx.x;
    if (c >= n4) return;
    const float4* src = which ? (const float4*)g_k : (const float4*)g_qext;
    uint2* hi = which ? (uint2*)g_kh : (uint2*)g_qh;
    uint2* lo = which ? (uint2*)g_kl : (uint2*)g_ql;
    float4 v = src[c];
    float lx, ly, lz, lw;
    uint2 h, l;
    h.x = split_hi(v.x, v.y, lx, ly);
    h.y = split_hi(v.z, v.w, lz, lw);
    l.x = pack2(__float2bfloat16(lx), __float2bfloat16(ly));
    l.y = pack2(__float2bfloat16(lz), __float2bfloat16(lw));
    hi[c] = h; lo[c] = l;
}

// ============ Kernel 4: transpose+convert V -> g_vth/g_vtl [bn][d][s] ============
__global__ __launch_bounds__(256) void vt_kernel()
{
    const int st = blockIdx.x, bn = blockIdx.y;
    __shared__ float tile[64][65];
    const int t = threadIdx.x;
#pragma unroll
    for (int c = 0; c < 4; c++) {
        int id = t + 256 * c, row = id >> 4, c4 = (id & 15) << 2;
        float4 v = *(const float4*)&g_v[((size_t)bn * SQ + st * 64 + row) * DH + c4];
        tile[row][c4 + 0] = v.x; tile[row][c4 + 1] = v.y;
        tile[row][c4 + 2] = v.z; tile[row][c4 + 3] = v.w;
    }
    __syncthreads();
#pragma unroll
    for (int c = 0; c < 4; c++) {
        int id = t + 256 * c, d = id >> 4, s4 = (id & 15) << 2;
        float f0 = tile[s4 + 0][d], f1 = tile[s4 + 1][d];
        float f2 = tile[s4 + 2][d], f3 = tile[s4 + 3][d];
        float l0, l1, l2, l3;
        uint2 hv, lv;
        hv.x = split_hi(f0, f1, l0, l1);
        hv.y = split_hi(f2, f3, l2, l3);
        lv.x = pack2(__float2bfloat16(l0), __float2bfloat16(l1));
        lv.y = pack2(__float2bfloat16(l2), __float2bfloat16(l3));
        size_t off = ((size_t)bn * DH + d) * SQ + st * 64 + s4;
        *(uint2*)&g_vth[off] = hv;
        *(uint2*)&g_vtl[off] = lv;
    }
}

// ============ Kernel 5: pack adj -> bitmask [r][b][jword][i] ============
__global__ __launch_bounds__(256) void pack_kernel(const float* __restrict__ adj)
{
    const int jw = blockIdx.x, b = blockIdx.y, r = blockIdx.z;
#pragma unroll
    for (int ii = 0; ii < 8; ii++) {
        int i = threadIdx.x + 256 * ii;
        const float* src = adj + (((size_t)(r * BB + b)) * SQ + i) * SQ + jw * 32;
        unsigned bits = 0;
#pragma unroll
        for (int e8 = 0; e8 < 8; e8++) {
            float4 v = *(const float4*)(src + e8 * 4);
            bits |= (unsigned)(v.x != 0.f) << (e8 * 4 + 0);
            bits |= (unsigned)(v.y != 0.f) << (e8 * 4 + 1);
            bits |= (unsigned)(v.z != 0.f) << (e8 * 4 + 2);
            bits |= (unsigned)(v.w != 0.f) << (e8 * 4 + 3);
        }
        g_adjbits[((size_t)(r * BB + b) * 64 + jw) * SQ + i] = bits;
    }
}

// ============ Kernel 6: fused flash (score + softmax + ctx) ============
// grid (NH, SQ/128, BB), block 256 (8 warps; warp w owns rows w*16..w*16+15, full j)
// SMEM: 12 Q tiles (slot x {hi,lo}, 128x64 bf16 = 16KB each), K hi/lo 8KB each, Vt hi/lo 8KB each
#define FQT(slot, half) (((slot) * 2 + (half)) * 16384)
#define FKT(half)       (196608 + (half) * 8192)
#define FVT(half)       (212992 + (half) * 8192)
#define FL_SMEM         229376
#define SWZ8(row, ch)   (((row) * 128) + ((((ch) ^ ((row) & 7))) << 4))

__global__ __launch_bounds__(256) void flash_kernel(
    const float* __restrict__ absb, const float* __restrict__ mask,
    float* __restrict__ out)
{
    extern __shared__ char smem[];
    const uint32_t sbase = smem_to_u32(smem);
    const int n = blockIdx.x, it = blockIdx.y, b = blockIdx.z;
    const int bn = b * NH + n;
    const int i0 = it * 128;
    const int tid = threadIdx.x, wid = tid >> 5, lane = tid & 31;
    const int m0 = wid * 16;

    // ---- load 12 Q tiles (128x64 bf16, swizzled) ----
#pragma unroll 4
    for (int c = 0; c < 48; c++) {
        int idx = tid + 256 * c;
        int tile = idx >> 10;               // 1024 uint4 per tile
        int rem = idx & 1023;
        int row = rem >> 3, ch = rem & 7;
        int slot = tile >> 1, half = tile & 1;
        const __nv_bfloat16* src = (half ? g_ql : g_qh) +
            (((size_t)slot * BN + bn) * SQ + i0 + row) * DH + ch * 8;
        *(uint4*)(smem + tile * 16384 + SWZ8(row, ch)) = *(const uint4*)src;
    }

    float ab[RR];
#pragma unroll
    for (int r = 0; r < RR; r++) ab[r] = absb[r * NH + n];

    const int rowA = m0 + (lane & 15);
    const int selA = lane >> 4;
    const int rowB8 = lane & 7;
    const int selB = (lane >> 3) & 1;
    const int c2 = 2 * (lane & 3);
    const int ia = i0 + m0 + (lane >> 2);   // global row a
    const int ib = ia + 8;                  // global row b

    float O[32];
#pragma unroll
    for (int e = 0; e < 32; e++) O[e] = 0.f;
    float mr[2] = {-1e30f, -1e30f};
    float lr[2] = {0.f, 0.f};

    for (int jt = 0; jt < 32; jt++) {
        __syncthreads();
        // ---- load K hi/lo (64x64) and Vt hi/lo (64d x 64j) ----
#pragma unroll
        for (int c = 0; c < 8; c++) {
            int idx = tid + 256 * c;
            int seg = idx >> 9;             // 0:kh 1:kl 2:vh 3:vl
            int rem = idx & 511;
            int row = rem >> 3, ch = rem & 7;
            const __nv_bfloat16* src;
            uint32_t dstoff;
            if (seg < 2) {
                src = (seg ? g_kl : g_kh) + ((size_t)bn * SQ + jt * 64 + row) * DH + ch * 8;
                dstoff = FKT(seg);
            } else {
                src = ((seg == 3) ? g_vtl : g_vth) + ((size_t)bn * DH + row) * SQ + jt * 64 + ch * 8;
                dstoff = FVT(seg - 2);
            }
            *(uint4*)(smem + dstoff + SWZ8(row, ch)) = *(const uint4*)src;
        }
        __syncthreads();

#pragma unroll
        for (int jh = 0; jh < 2; jh++) {
            // ---- hoist K fragments [half][ks][nf][2] ----
            uint32_t BK[2][4][4][2];
#pragma unroll
            for (int h = 0; h < 2; h++)
#pragma unroll
                for (int ks = 0; ks < 4; ks++)
#pragma unroll
                    for (int nf = 0; nf < 4; nf++)
                        ldsm_x2(BK[h][ks][nf],
                                sbase + FKT(h) + SWZ8(jh * 32 + nf * 8 + rowB8, ks * 2 + selB));

            const int jw = jt * 2 + jh;
            unsigned aw1[RR], aw2[RR];
#pragma unroll
            for (int r = 0; r < RR; r++) {
                aw1[r] = g_adjbits[((size_t)(r * BB + b) * 64 + jw) * SQ + ia];
                aw2[r] = g_adjbits[((size_t)(r * BB + b) * 64 + jw) * SQ + ib];
            }

            float fin[16];
#pragma unroll
            for (int s = 0; s < 6; s++) {
                float tmp[16] = {};
#pragma unroll
                for (int ks = 0; ks < 4; ks++) {
                    uint32_t Ah[4], Al[4];
                    ldsm_x4(Ah, sbase + FQT(s, 0) + SWZ8(rowA, ks * 2 + selA));
                    ldsm_x4(Al, sbase + FQT(s, 1) + SWZ8(rowA, ks * 2 + selA));
#pragma unroll
                    for (int nf = 0; nf < 4; nf++) {
                        mma16816(tmp + nf * 4, Ah, BK[0][ks][nf]);
                        mma16816(tmp + nf * 4, Ah, BK[1][ks][nf]);
                        mma16816(tmp + nf * 4, Al, BK[0][ks][nf]);
                    }
                }
                if (s == 0) {
#pragma unroll
                    for (int e = 0; e < 16; e++) fin[e] = tmp[e];
                } else {
                    const int r = s - 1;
                    const float abr = ab[r];
#pragma unroll
                    for (int nf = 0; nf < 4; nf++) {
                        int sh = nf * 8 + c2;
                        if ((aw1[r] >> sh) & 1)       fin[nf * 4 + 0] += tmp[nf * 4 + 0] + abr;
                        if ((aw1[r] >> (sh + 1)) & 1) fin[nf * 4 + 1] += tmp[nf * 4 + 1] + abr;
                        if ((aw2[r] >> sh) & 1)       fin[nf * 4 + 2] += tmp[nf * 4 + 2] + abr;
                        if ((aw2[r] >> (sh + 1)) & 1) fin[nf * 4 + 3] += tmp[nf * 4 + 3] + abr;
                    }
                }
            }

            // ---- scale + additive mask ----
#pragma unroll
            for (int nf = 0; nf < 4; nf++) {
                float2 mk = __ldg((const float2*)&mask[b * SQ + jt * 64 + jh * 32 + nf * 8 + c2]);
                fin[nf * 4 + 0] = fin[nf * 4 + 0] * 0.125f + mk.x;
                fin[nf * 4 + 1] = fin[nf * 4 + 1] * 0.125f + mk.y;
                fin[nf * 4 + 2] = fin[nf * 4 + 2] * 0.125f + mk.x;
                fin[nf * 4 + 3] = fin[nf * 4 + 3] * 0.125f + mk.y;
            }

            // ---- online softmax update (32-j chunk) ----
            float mxa = -1e30f, mxb = -1e30f;
#pragma unroll
            for (int nf = 0; nf < 4; nf++) {
                mxa = fmaxf(mxa, fmaxf(fin[nf * 4 + 0], fin[nf * 4 + 1]));
                mxb = fmaxf(mxb, fmaxf(fin[nf * 4 + 2], fin[nf * 4 + 3]));
            }
            mxa = fmaxf(mxa, __shfl_xor_sync(0xffffffffu, mxa, 1));
            mxa = fmaxf(mxa, __shfl_xor_sync(0xffffffffu, mxa, 2));
            mxb = fmaxf(mxb, __shfl_xor_sync(0xffffffffu, mxb, 1));
            mxb = fmaxf(mxb, __shfl_xor_sync(0xffffffffu, mxb, 2));
            float mna = fmaxf(mr[0], mxa), mnb = fmaxf(mr[1], mxb);
            float ala = __expf(mr[0] - mna), alb = __expf(mr[1] - mnb);
            mr[0] = mna; mr[1] = mnb;

            float sa = 0.f, sb = 0.f;
#pragma unroll
            for (int nf = 0; nf < 4; nf++) {
                fin[nf * 4 + 0] = __expf(fin[nf * 4 + 0] - mna);
                fin[nf * 4 + 1] = __expf(fin[nf * 4 + 1] - mna);
                fin[nf * 4 + 2] = __expf(fin[nf * 4 + 2] - mnb);
                fin[nf * 4 + 3] = __expf(fin[nf * 4 + 3] - mnb);
                sa += fin[nf * 4 + 0] + fin[nf * 4 + 1];
                sb += fin[nf * 4 + 2] + fin[nf * 4 + 3];
            }
            sa += __shfl_xor_sync(0xffffffffu, sa, 1);
            sa += __shfl_xor_sync(0xffffffffu, sa, 2);
            sb += __shfl_xor_sync(0xffffffffu, sb, 1);
            sb += __shfl_xor_sync(0xffffffffu, sb, 2);
            lr[0] = lr[0] * ala + sa;
            lr[1] = lr[1] * alb + sb;

            // rescale O
#pragma unroll
            for (int dn = 0; dn < 8; dn++) {
                O[dn * 4 + 0] *= ala; O[dn * 4 + 1] *= ala;
                O[dn * 4 + 2] *= alb; O[dn * 4 + 3] *= alb;
            }

            // ---- pack P into A-fragments (hi/lo) ----
            uint32_t Ph[2][4], Pl[2][4];
#pragma unroll
            for (int jk = 0; jk < 2; jk++) {
                float l0, l1;
                Ph[jk][0] = split_hi(fin[(2 * jk) * 4 + 0], fin[(2 * jk) * 4 + 1], l0, l1);
                Pl[jk][0] = pack2(__float2bfloat16(l0), __float2bfloat16(l1));
                Ph[jk][1] = split_hi(fin[(2 * jk) * 4 + 2], fin[(2 * jk) * 4 + 3], l0, l1);
                Pl[jk][1] = pack2(__float2bfloat16(l0), __float2bfloat16(l1));
                Ph[jk][2] = split_hi(fin[(2 * jk + 1) * 4 + 0], fin[(2 * jk + 1) * 4 + 1], l0, l1);
                Pl[jk][2] = pack2(__float2bfloat16(l0), __float2bfloat16(l1));
                Ph[jk][3] = split_hi(fin[(2 * jk + 1) * 4 + 2], fin[(2 * jk + 1) * 4 + 3], l0, l1);
                Pl[jk][3] = pack2(__float2bfloat16(l0), __float2bfloat16(l1));
            }

            // ---- P @ V accumulate into O ----
#pragma unroll
            for (int jk = 0; jk < 2; jk++) {
#pragma unroll
                for (int dn = 0; dn < 8; dn++) {
                    uint32_t BVh[2], BVl[2];
                    ldsm_x2(BVh, sbase + FVT(0) + SWZ8(dn * 8 + rowB8, jh * 4 + jk * 2 + selB));
                    ldsm_x2(BVl, sbase + FVT(1) + SWZ8(dn * 8 + rowB8, jh * 4 + jk * 2 + selB));
                    mma16816(O + dn * 4, Ph[jk], BVh);
                    mma16816(O + dn * 4, Ph[jk], BVl);
                    mma16816(O + dn * 4, Pl[jk], BVh);
                }
            }
        }
    }

    // ---- finalize: O / l, write out[b][i][n*64+d] ----
    const float inva = 1.0f / lr[0], invb = 1.0f / lr[1];
#pragma unroll
    for (int dn = 0; dn < 8; dn++) {
        int d = dn * 8 + c2;
        float2 oa, ob;
        oa.x = O[dn * 4 + 0] * inva; oa.y = O[dn * 4 + 1] * inva;
        ob.x = O[dn * 4 + 2] * invb; ob.y = O[dn * 4 + 3] * invb;
        *(float2*)&out[((size_t)b * SQ + ia) * HID + n * 64 + d] = oa;
        *(float2*)&out[((size_t)b * SQ + ib) * HID + n * 64 + d] = ob;
    }
}

// =================================================================
extern "C" void kernel_launch(void* const* d_in, const int* in_sizes, int n_in,
                              void* d_out, int out_size)
{
    const float* hidden = (const float*)d_in[0];
    const float* mask   = (const float*)d_in[1];
    const float* adj    = (const float*)d_in[2];
    const float* Wq     = (const float*)d_in[3];
    const float* bq     = (const float*)d_in[4];
    const float* Wk     = (const float*)d_in[5];
    const float* bk     = (const float*)d_in[6];
    const float* Wv     = (const float*)d_in[7];
    const float* bv     = (const float*)d_in[8];
    const float* bili   = (const float*)d_in[9];
    const float* absb   = (const float*)d_in[10];
    float* out = (float*)d_out;
    (void)in_sizes; (void)n_in; (void)out_size;

    cudaFuncSetAttribute(flash_kernel, cudaFuncAttributeMaxDynamicSharedMemorySize, FL_SMEM);

    proj_kernel<<<dim3(HID / 64, (BB * SQ) / 64, 3), 256>>>(hidden, Wq, Wk, Wv, bq, bk, bv);
    qb_kernel<<<dim3(SQ / 64, BN, RR), 256>>>(bili);
    conv_kernel<<<(6 * BN * SQ * DH / 4 + 255) / 256, 256>>>(0, 6 * BN * SQ * DH / 4);
    conv_kernel<<<(BN * SQ * DH / 4 + 255) / 256, 256>>>(1, BN * SQ * DH / 4);
    vt_kernel<<<dim3(SQ / 64, BN), 256>>>();
    pack_kernel<<<dim3(SQ / 32, BB, RR), 256>>>(adj);
    flash_kernel<<<dim3(NH, SQ / 128, BB), 256, FL_SMEM>>>(absb, mask, out);
}

// round 6
// speedup vs baseline: 2.5468x; 1.2303x over previous
#include <cuda_runtime.h>
#include <cuda_bf16.h>
#include <cstdint>
#include <math.h>

#define SQ   2048
#define HID  768
#define BB   2
#define NH   12
#define DH   64
#define RR   5
#define BN   24

// ---------------- device scratch ----------------
__device__ float g_v   [(size_t)BN * SQ * DH];
__device__ __nv_bfloat16 g_xh[(size_t)BB * SQ * HID];
__device__ __nv_bfloat16 g_xl[(size_t)BB * SQ * HID];
__device__ __nv_bfloat16 g_wh[(size_t)3 * HID * HID];
__device__ __nv_bfloat16 g_wl[(size_t)3 * HID * HID];
__device__ __nv_bfloat16 g_qh[(size_t)6 * BN * SQ * DH];
__device__ __nv_bfloat16 g_ql[(size_t)6 * BN * SQ * DH];
__device__ __nv_bfloat16 g_kh[(size_t)BN * SQ * DH];
__device__ __nv_bfloat16 g_kl[(size_t)BN * SQ * DH];
__device__ __nv_bfloat16 g_vth[(size_t)BN * DH * SQ];   // V^T [bn][d][s] hi
__device__ __nv_bfloat16 g_vtl[(size_t)BN * DH * SQ];   // V^T [bn][d][s] lo
__device__ unsigned g_adjbits[(size_t)RR * BB * (SQ / 32) * SQ];

// ================= helpers =================
__device__ __forceinline__ uint32_t smem_to_u32(const void* p) {
    uint32_t a;
    asm("{ .reg .u64 t; cvta.to.shared.u64 t, %1; cvt.u32.u64 %0, t; }" : "=r"(a) : "l"(p));
    return a;
}
__device__ __forceinline__ unsigned pack2(__nv_bfloat16 a, __nv_bfloat16 b) {
    __nv_bfloat162 t; t.x = a; t.y = b;
    return *reinterpret_cast<unsigned*>(&t);
}
__device__ __forceinline__ void ldsm_x4(uint32_t* r, uint32_t addr) {
    asm volatile("ldmatrix.sync.aligned.m8n8.x4.shared.b16 {%0,%1,%2,%3}, [%4];"
        : "=r"(r[0]), "=r"(r[1]), "=r"(r[2]), "=r"(r[3]) : "r"(addr));
}
__device__ __forceinline__ void ldsm_x2(uint32_t* r, uint32_t addr) {
    asm volatile("ldmatrix.sync.aligned.m8n8.x2.shared.b16 {%0,%1}, [%2];"
        : "=r"(r[0]), "=r"(r[1]) : "r"(addr));
}
__device__ __forceinline__ void mma16816(float* d, const uint32_t* a, const uint32_t* b) {
    asm volatile(
        "mma.sync.aligned.m16n8k16.row.col.f32.bf16.bf16.f32 "
        "{%0,%1,%2,%3}, {%4,%5,%6,%7}, {%8,%9}, {%0,%1,%2,%3};"
        : "+f"(d[0]), "+f"(d[1]), "+f"(d[2]), "+f"(d[3])
        : "r"(a[0]), "r"(a[1]), "r"(a[2]), "r"(a[3]), "r"(b[0]), "r"(b[1]));
}
__device__ __forceinline__ unsigned split_hi(float x, float y, float& lx, float& ly) {
    __nv_bfloat16 hx = __float2bfloat16(x), hy = __float2bfloat16(y);
    lx = x - __bfloat162float(hx);
    ly = y - __bfloat162float(hy);
    return pack2(hx, hy);
}
#define SWZ8(row, ch)   (((row) * 128) + ((((ch) ^ ((row) & 7))) << 4))

// ============ conv X -> bf16 hi/lo ============
__global__ __launch_bounds__(256) void convx_kernel(const float* __restrict__ X)
{
    int c = blockIdx.x * 256 + threadIdx.x;   // over BB*SQ*HID/4 float4
    float4 v = ((const float4*)X)[c];
    float lx, ly, lz, lw;
    uint2 h, l;
    h.x = split_hi(v.x, v.y, lx, ly);
    h.y = split_hi(v.z, v.w, lz, lw);
    l.x = pack2(__float2bfloat16(lx), __float2bfloat16(ly));
    l.y = pack2(__float2bfloat16(lz), __float2bfloat16(lw));
    ((uint2*)g_xh)[c] = h;
    ((uint2*)g_xl)[c] = l;
}

// ============ conv W (q,k,v) -> bf16 hi/lo ============
__global__ __launch_bounds__(256) void convw_kernel(
    const float* __restrict__ Wq, const float* __restrict__ Wk, const float* __restrict__ Wv)
{
    const int per = HID * HID / 4;
    int c = blockIdx.x * 256 + threadIdx.x;   // over 3*per
    int z = c / per;
    const float* W = (z == 0) ? Wq : (z == 1) ? Wk : Wv;
    float4 v = ((const float4*)W)[c - z * per];
    float lx, ly, lz, lw;
    uint2 h, l;
    h.x = split_hi(v.x, v.y, lx, ly);
    h.y = split_hi(v.z, v.w, lz, lw);
    l.x = pack2(__float2bfloat16(lx), __float2bfloat16(ly));
    l.y = pack2(__float2bfloat16(lz), __float2bfloat16(lw));
    ((uint2*)g_wh)[c] = h;
    ((uint2*)g_wl)[c] = l;
}

// ============ proj via HMMA: out = X @ W^T + b ============
// grid (12 otile, 32 mtile-of-128, 3 z), block 256 (8 warps x 16 rows)
#define PJ_XH 0
#define PJ_XL 16384
#define PJ_WH 32768
#define PJ_WL 40960
#define PJ_SMEM 49152

__global__ __launch_bounds__(256) void proj_mma_kernel(
    const float* __restrict__ bq, const float* __restrict__ bk, const float* __restrict__ bv)
{
    extern __shared__ char smem[];
    const uint32_t sbase = smem_to_u32(smem);
    const int otile = blockIdx.x, mtile = blockIdx.y, z = blockIdx.z;
    const float* bias = (z == 0) ? bq : (z == 1) ? bk : bv;
    const int tid = threadIdx.x, wid = tid >> 5, lane = tid & 31;
    const int m0 = wid * 16;
    const int rowA = m0 + (lane & 15);
    const int selA = lane >> 4;
    const int rowB8 = lane & 7;
    const int selB = (lane >> 3) & 1;
    const int c2 = 2 * (lane & 3);

    float fin[32];
#pragma unroll
    for (int e = 0; e < 32; e++) fin[e] = 0.f;

    for (int kc = 0; kc < HID / 64; kc++) {
        __syncthreads();
        // X tiles: 2 x 1024 uint4
#pragma unroll
        for (int c = 0; c < 8; c++) {
            int idx = tid + 256 * c;
            int half = idx >> 10;
            int rem = idx & 1023;
            int row = rem >> 3, ch = rem & 7;
            const __nv_bfloat16* src = (half ? g_xl : g_xh) +
                (size_t)(mtile * 128 + row) * HID + kc * 64 + ch * 8;
            *(uint4*)(smem + (half ? PJ_XL : PJ_XH) + SWZ8(row, ch)) = *(const uint4*)src;
        }
        // W tiles: 2 x 512 uint4
#pragma unroll
        for (int c = 0; c < 4; c++) {
            int idx = tid + 256 * c;
            int half = idx >> 9;
            int rem = idx & 511;
            int row = rem >> 3, ch = rem & 7;
            const __nv_bfloat16* src = (half ? g_wl : g_wh) +
                ((size_t)z * HID + otile * 64 + row) * HID + kc * 64 + ch * 8;
            *(uint4*)(smem + (half ? PJ_WL : PJ_WH) + SWZ8(row, ch)) = *(const uint4*)src;
        }
        __syncthreads();

#pragma unroll
        for (int ks = 0; ks < 4; ks++) {
            uint32_t Ah[4], Al[4];
            ldsm_x4(Ah, sbase + PJ_XH + SWZ8(rowA, ks * 2 + selA));
            ldsm_x4(Al, sbase + PJ_XL + SWZ8(rowA, ks * 2 + selA));
#pragma unroll
            for (int nf = 0; nf < 8; nf++) {
                uint32_t Bh[2], Bl[2];
                ldsm_x2(Bh, sbase + PJ_WH + SWZ8(nf * 8 + rowB8, ks * 2 + selB));
                ldsm_x2(Bl, sbase + PJ_WL + SWZ8(nf * 8 + rowB8, ks * 2 + selB));
                mma16816(fin + nf * 4, Ah, Bh);
                mma16816(fin + nf * 4, Ah, Bl);
                mma16816(fin + nf * 4, Al, Bh);
            }
        }
    }

    // epilogue
    const int ma = mtile * 128 + m0 + (lane >> 2);
    const int mb = ma + 8;
    const int b = ma >> 11;
    const int sa = ma & (SQ - 1), sb = sa + 8;
    const int bn = b * NH + otile;
#pragma unroll
    for (int nf = 0; nf < 8; nf++) {
        int col = nf * 8 + c2;
        float bsx = bias[otile * 64 + col], bsy = bias[otile * 64 + col + 1];
        float a0 = fin[nf * 4 + 0] + bsx, a1 = fin[nf * 4 + 1] + bsy;
        float b0 = fin[nf * 4 + 2] + bsx, b1 = fin[nf * 4 + 3] + bsy;
        size_t offa = ((size_t)bn * SQ + sa) * DH + col;
        size_t offb = ((size_t)bn * SQ + sb) * DH + col;
        if (z == 2) {
            *(float2*)&g_v[offa] = make_float2(a0, a1);
            *(float2*)&g_v[offb] = make_float2(b0, b1);
        } else {
            __nv_bfloat16* dh = (z == 0) ? g_qh : g_kh;
            __nv_bfloat16* dl = (z == 0) ? g_ql : g_kl;
            float l0, l1;
            unsigned h;
            h = split_hi(a0, a1, l0, l1);
            *(unsigned*)&dh[offa] = h;
            *(unsigned*)&dl[offa] = pack2(__float2bfloat16(l0), __float2bfloat16(l1));
            h = split_hi(b0, b1, l0, l1);
            *(unsigned*)&dh[offb] = h;
            *(unsigned*)&dl[offb] = pack2(__float2bfloat16(l0), __float2bfloat16(l1));
        }
    }
}

// ============ qb via HMMA: q'_r = q @ bili[r,n] ============
// grid (16 itile-of-128, 24 bn, 5 r), block 256
#define QB_QH 0
#define QB_QL 16384
#define QB_BH 32768
#define QB_BL 40960
#define QB_SMEM 49152

__global__ __launch_bounds__(256) void qb_mma_kernel(const float* __restrict__ bili)
{
    extern __shared__ char smem[];
    const uint32_t sbase = smem_to_u32(smem);
    const int it = blockIdx.x, bn = blockIdx.y, r = blockIdx.z;
    const int n = bn % NH;
    const int tid = threadIdx.x, wid = tid >> 5, lane = tid & 31;
    const int m0 = wid * 16;
    const int rowA = m0 + (lane & 15);
    const int selA = lane >> 4;
    const int rowB8 = lane & 7;
    const int selB = (lane >> 3) & 1;
    const int c2 = 2 * (lane & 3);

    // load q tiles (slot 0) hi/lo: 2 x 1024 uint4
#pragma unroll
    for (int c = 0; c < 8; c++) {
        int idx = tid + 256 * c;
        int half = idx >> 10;
        int rem = idx & 1023;
        int row = rem >> 3, ch = rem & 7;
        const __nv_bfloat16* src = (half ? g_ql : g_qh) +
            ((size_t)bn * SQ + it * 128 + row) * DH + ch * 8;
        *(uint4*)(smem + (half ? QB_QL : QB_QH) + SWZ8(row, ch)) = *(const uint4*)src;
    }
    // load bili[r][n] transposed + split: bs[t][p] = bili[p][t]
    const float* bb = bili + ((size_t)r * NH + n) * DH * DH;
#pragma unroll
    for (int c = 0; c < 16; c++) {
        int id = tid + 256 * c;
        int p = id >> 6, t = id & 63;
        float v = bb[p * 64 + t];
        float lo;
        __nv_bfloat16 hv = __float2bfloat16(v);
        lo = v - __bfloat162float(hv);
        uint32_t byteoff = SWZ8(t, p >> 3) + (p & 7) * 2;
        *(__nv_bfloat16*)(smem + QB_BH + byteoff) = hv;
        *(__nv_bfloat16*)(smem + QB_BL + byteoff) = __float2bfloat16(lo);
    }
    __syncthreads();

    float fin[32];
#pragma unroll
    for (int e = 0; e < 32; e++) fin[e] = 0.f;

#pragma unroll
    for (int ks = 0; ks < 4; ks++) {
        uint32_t Ah[4], Al[4];
        ldsm_x4(Ah, sbase + QB_QH + SWZ8(rowA, ks * 2 + selA));
        ldsm_x4(Al, sbase + QB_QL + SWZ8(rowA, ks * 2 + selA));
#pragma unroll
        for (int nf = 0; nf < 8; nf++) {
            uint32_t Bh[2], Bl[2];
            ldsm_x2(Bh, sbase + QB_BH + SWZ8(nf * 8 + rowB8, ks * 2 + selB));
            ldsm_x2(Bl, sbase + QB_BL + SWZ8(nf * 8 + rowB8, ks * 2 + selB));
            mma16816(fin + nf * 4, Ah, Bh);
            mma16816(fin + nf * 4, Ah, Bl);
            mma16816(fin + nf * 4, Al, Bh);
        }
    }

    // epilogue: write slot 1+r hi/lo
    const int slot = 1 + r;
    const int ia = it * 128 + m0 + (lane >> 2);
    const int ib = ia + 8;
#pragma unroll
    for (int nf = 0; nf < 8; nf++) {
        int col = nf * 8 + c2;
        size_t offa = (((size_t)slot * BN + bn) * SQ + ia) * DH + col;
        size_t offb = (((size_t)slot * BN + bn) * SQ + ib) * DH + col;
        float l0, l1;
        unsigned h;
        h = split_hi(fin[nf * 4 + 0], fin[nf * 4 + 1], l0, l1);
        *(unsigned*)&g_qh[offa] = h;
        *(unsigned*)&g_ql[offa] = pack2(__float2bfloat16(l0), __float2bfloat16(l1));
        h = split_hi(fin[nf * 4 + 2], fin[nf * 4 + 3], l0, l1);
        *(unsigned*)&g_qh[offb] = h;
        *(unsigned*)&g_ql[offb] = pack2(__float2bfloat16(l0), __float2bfloat16(l1));
    }
}

// ============ transpose+convert V -> g_vth/g_vtl [bn][d][s] ============
__global__ __launch_bounds__(256) void vt_kernel()
{
    const int st = blockIdx.x, bn = blockIdx.y;
    __shared__ float tile[64][65];
    const int t = threadIdx.x;
#pragma unroll
    for (int c = 0; c < 4; c++) {
        int id = t + 256 * c, row = id >> 4, c4 = (id & 15) << 2;
        float4 v = *(const float4*)&g_v[((size_t)bn * SQ + st * 64 + row) * DH + c4];
        tile[row][c4 + 0] = v.x; tile[row][c4 + 1] = v.y;
        tile[row][c4 + 2] = v.z; tile[row][c4 + 3] = v.w;
    }
    __syncthreads();
#pragma unroll
    for (int c = 0; c < 4; c++) {
        int id = t + 256 * c, d = id >> 4, s4 = (id & 15) << 2;
        float f0 = tile[s4 + 0][d], f1 = tile[s4 + 1][d];
        float f2 = tile[s4 + 2][d], f3 = tile[s4 + 3][d];
        float l0, l1, l2, l3;
        uint2 hv, lv;
        hv.x = split_hi(f0, f1, l0, l1);
        hv.y = split_hi(f2, f3, l2, l3);
        lv.x = pack2(__float2bfloat16(l0), __float2bfloat16(l1));
        lv.y = pack2(__float2bfloat16(l2), __float2bfloat16(l3));
        size_t off = ((size_t)bn * DH + d) * SQ + st * 64 + s4;
        *(uint2*)&g_vth[off] = hv;
        *(uint2*)&g_vtl[off] = lv;
    }
}

// ============ pack adj -> bitmask [r][b][jword][i] ============
__global__ __launch_bounds__(256) void pack_kernel(const float* __restrict__ adj)
{
    const int jw = blockIdx.x, b = blockIdx.y, r = blockIdx.z;
#pragma unroll
    for (int ii = 0; ii < 8; ii++) {
        int i = threadIdx.x + 256 * ii;
        const float* src = adj + (((size_t)(r * BB + b)) * SQ + i) * SQ + jw * 32;
        unsigned bits = 0;
#pragma unroll
        for (int e8 = 0; e8 < 8; e8++) {
            float4 v = *(const float4*)(src + e8 * 4);
            bits |= (unsigned)(v.x != 0.f) << (e8 * 4 + 0);
            bits |= (unsigned)(v.y != 0.f) << (e8 * 4 + 1);
            bits |= (unsigned)(v.z != 0.f) << (e8 * 4 + 2);
            bits |= (unsigned)(v.w != 0.f) << (e8 * 4 + 3);
        }
        g_adjbits[((size_t)(r * BB + b) * 64 + jw) * SQ + i] = bits;
    }
}

// ============ fused flash (score + softmax + ctx) ============
#define FQT(slot, half) (((slot) * 2 + (half)) * 16384)
#define FKT(half)       (196608 + (half) * 8192)
#define FVT(half)       (212992 + (half) * 8192)
#define FL_SMEM         229376

__global__ __launch_bounds__(256) void flash_kernel(
    const float* __restrict__ absb, const float* __restrict__ mask,
    float* __restrict__ out)
{
    extern __shared__ char smem[];
    const uint32_t sbase = smem_to_u32(smem);
    const int n = blockIdx.x, it = blockIdx.y, b = blockIdx.z;
    const int bn = b * NH + n;
    const int i0 = it * 128;
    const int tid = threadIdx.x, wid = tid >> 5, lane = tid & 31;
    const int m0 = wid * 16;

#pragma unroll 4
    for (int c = 0; c < 48; c++) {
        int idx = tid + 256 * c;
        int tile = idx >> 10;
        int rem = idx & 1023;
        int row = rem >> 3, ch = rem & 7;
        int slot = tile >> 1, half = tile & 1;
        const __nv_bfloat16* src = (half ? g_ql : g_qh) +
            (((size_t)slot * BN + bn) * SQ + i0 + row) * DH + ch * 8;
        *(uint4*)(smem + tile * 16384 + SWZ8(row, ch)) = *(const uint4*)src;
    }

    float ab[RR];
#pragma unroll
    for (int r = 0; r < RR; r++) ab[r] = absb[r * NH + n];

    const int rowA = m0 + (lane & 15);
    const int selA = lane >> 4;
    const int rowB8 = lane & 7;
    const int selB = (lane >> 3) & 1;
    const int c2 = 2 * (lane & 3);
    const int ia = i0 + m0 + (lane >> 2);
    const int ib = ia + 8;

    float O[32];
#pragma unroll
    for (int e = 0; e < 32; e++) O[e] = 0.f;
    float mr[2] = {-1e30f, -1e30f};
    float lr[2] = {0.f, 0.f};

    for (int jt = 0; jt < 32; jt++) {
        __syncthreads();
#pragma unroll
        for (int c = 0; c < 8; c++) {
            int idx = tid + 256 * c;
            int seg = idx >> 9;
            int rem = idx & 511;
            int row = rem >> 3, ch = rem & 7;
            const __nv_bfloat16* src;
            uint32_t dstoff;
            if (seg < 2) {
                src = (seg ? g_kl : g_kh) + ((size_t)bn * SQ + jt * 64 + row) * DH + ch * 8;
                dstoff = FKT(seg);
            } else {
                src = ((seg == 3) ? g_vtl : g_vth) + ((size_t)bn * DH + row) * SQ + jt * 64 + ch * 8;
                dstoff = FVT(seg - 2);
            }
            *(uint4*)(smem + dstoff + SWZ8(row, ch)) = *(const uint4*)src;
        }
        __syncthreads();

#pragma unroll
        for (int jh = 0; jh < 2; jh++) {
            uint32_t BK[2][4][4][2];
#pragma unroll
            for (int h = 0; h < 2; h++)
#pragma unroll
                for (int ks = 0; ks < 4; ks++)
#pragma unroll
                    for (int nf = 0; nf < 4; nf++)
                        ldsm_x2(BK[h][ks][nf],
                                sbase + FKT(h) + SWZ8(jh * 32 + nf * 8 + rowB8, ks * 2 + selB));

            const int jw = jt * 2 + jh;
            unsigned aw1[RR], aw2[RR];
#pragma unroll
            for (int r = 0; r < RR; r++) {
                aw1[r] = g_adjbits[((size_t)(r * BB + b) * 64 + jw) * SQ + ia];
                aw2[r] = g_adjbits[((size_t)(r * BB + b) * 64 + jw) * SQ + ib];
            }

            float fin[16];
#pragma unroll
            for (int s = 0; s < 6; s++) {
                float tmp[16] = {};
#pragma unroll
                for (int ks = 0; ks < 4; ks++) {
                    uint32_t Ah[4], Al[4];
                    ldsm_x4(Ah, sbase + FQT(s, 0) + SWZ8(rowA, ks * 2 + selA));
                    ldsm_x4(Al, sbase + FQT(s, 1) + SWZ8(rowA, ks * 2 + selA));
#pragma unroll
                    for (int nf = 0; nf < 4; nf++) {
                        mma16816(tmp + nf * 4, Ah, BK[0][ks][nf]);
                        mma16816(tmp + nf * 4, Ah, BK[1][ks][nf]);
                        mma16816(tmp + nf * 4, Al, BK[0][ks][nf]);
                    }
                }
                if (s == 0) {
#pragma unroll
                    for (int e = 0; e < 16; e++) fin[e] = tmp[e];
                } else {
                    const int r = s - 1;
                    const float abr = ab[r];
#pragma unroll
                    for (int nf = 0; nf < 4; nf++) {
                        int sh = nf * 8 + c2;
                        if ((aw1[r] >> sh) & 1)       fin[nf * 4 + 0] += tmp[nf * 4 + 0] + abr;
                        if ((aw1[r] >> (sh + 1)) & 1) fin[nf * 4 + 1] += tmp[nf * 4 + 1] + abr;
                        if ((aw2[r] >> sh) & 1)       fin[nf * 4 + 2] += tmp[nf * 4 + 2] + abr;
                        if ((aw2[r] >> (sh + 1)) & 1) fin[nf * 4 + 3] += tmp[nf * 4 + 3] + abr;
                    }
                }
            }

#pragma unroll
            for (int nf = 0; nf < 4; nf++) {
                float2 mk = __ldg((const float2*)&mask[b * SQ + jt * 64 + jh * 32 + nf * 8 + c2]);
                fin[nf * 4 + 0] = fin[nf * 4 + 0] * 0.125f + mk.x;
                fin[nf * 4 + 1] = fin[nf * 4 + 1] * 0.125f + mk.y;
                fin[nf * 4 + 2] = fin[nf * 4 + 2] * 0.125f + mk.x;
                fin[nf * 4 + 3] = fin[nf * 4 + 3] * 0.125f + mk.y;
            }

            float mxa = -1e30f, mxb = -1e30f;
#pragma unroll
            for (int nf = 0; nf < 4; nf++) {
                mxa = fmaxf(mxa, fmaxf(fin[nf * 4 + 0], fin[nf * 4 + 1]));
                mxb = fmaxf(mxb, fmaxf(fin[nf * 4 + 2], fin[nf * 4 + 3]));
            }
            mxa = fmaxf(mxa, __shfl_xor_sync(0xffffffffu, mxa, 1));
            mxa = fmaxf(mxa, __shfl_xor_sync(0xffffffffu, mxa, 2));
            mxb = fmaxf(mxb, __shfl_xor_sync(0xffffffffu, mxb, 1));
            mxb = fmaxf(mxb, __shfl_xor_sync(0xffffffffu, mxb, 2));
            float mna = fmaxf(mr[0], mxa), mnb = fmaxf(mr[1], mxb);
            float ala = __expf(mr[0] - mna), alb = __expf(mr[1] - mnb);
            mr[0] = mna; mr[1] = mnb;

            float sa = 0.f, sb = 0.f;
#pragma unroll
            for (int nf = 0; nf < 4; nf++) {
                fin[nf * 4 + 0] = __expf(fin[nf * 4 + 0] - mna);
                fin[nf * 4 + 1] = __expf(fin[nf * 4 + 1] - mna);
                fin[nf * 4 + 2] = __expf(fin[nf * 4 + 2] - mnb);
                fin[nf * 4 + 3] = __expf(fin[nf * 4 + 3] - mnb);
                sa += fin[nf * 4 + 0] + fin[nf * 4 + 1];
                sb += fin[nf * 4 + 2] + fin[nf * 4 + 3];
            }
            sa += __shfl_xor_sync(0xffffffffu, sa, 1);
            sa += __shfl_xor_sync(0xffffffffu, sa, 2);
            sb += __shfl_xor_sync(0xffffffffu, sb, 1);
            sb += __shfl_xor_sync(0xffffffffu, sb, 2);
            lr[0] = lr[0] * ala + sa;
            lr[1] = lr[1] * alb + sb;

#pragma unroll
            for (int dn = 0; dn < 8; dn++) {
                O[dn * 4 + 0] *= ala; O[dn * 4 + 1] *= ala;
                O[dn * 4 + 2] *= alb; O[dn * 4 + 3] *= alb;
            }

            uint32_t Ph[2][4], Pl[2][4];
#pragma unroll
            for (int jk = 0; jk < 2; jk++) {
                float l0, l1;
                Ph[jk][0] = split_hi(fin[(2 * jk) * 4 + 0], fin[(2 * jk) * 4 + 1], l0, l1);
                Pl[jk][0] = pack2(__float2bfloat16(l0), __float2bfloat16(l1));
                Ph[jk][1] = split_hi(fin[(2 * jk) * 4 + 2], fin[(2 * jk) * 4 + 3], l0, l1);
                Pl[jk][1] = pack2(__float2bfloat16(l0), __float2bfloat16(l1));
                Ph[jk][2] = split_hi(fin[(2 * jk + 1) * 4 + 0], fin[(2 * jk + 1) * 4 + 1], l0, l1);
                Pl[jk][2] = pack2(__float2bfloat16(l0), __float2bfloat16(l1));
                Ph[jk][3] = split_hi(fin[(2 * jk + 1) * 4 + 2], fin[(2 * jk + 1) * 4 + 3], l0, l1);
                Pl[jk][3] = pack2(__float2bfloat16(l0), __float2bfloat16(l1));
            }

#pragma unroll
            for (int jk = 0; jk < 2; jk++) {
#pragma unroll
                for (int dn = 0; dn < 8; dn++) {
                    uint32_t BVh[2], BVl[2];
                    ldsm_x2(BVh, sbase + FVT(0) + SWZ8(dn * 8 + rowB8, jh * 4 + jk * 2 + selB));
                    ldsm_x2(BVl, sbase + FVT(1) + SWZ8(dn * 8 + rowB8, jh * 4 + jk * 2 + selB));
                    mma16816(O + dn * 4, Ph[jk], BVh);
                    mma16816(O + dn * 4, Ph[jk], BVl);
                    mma16816(O + dn * 4, Pl[jk], BVh);
                }
            }
        }
    }

    const float inva = 1.0f / lr[0], invb = 1.0f / lr[1];
#pragma unroll
    for (int dn = 0; dn < 8; dn++) {
        int d = dn * 8 + c2;
        float2 oa, ob;
        oa.x = O[dn * 4 + 0] * inva; oa.y = O[dn * 4 + 1] * inva;
        ob.x = O[dn * 4 + 2] * invb; ob.y = O[dn * 4 + 3] * invb;
        *(float2*)&out[((size_t)b * SQ + ia) * HID + n * 64 + d] = oa;
        *(float2*)&out[((size_t)b * SQ + ib) * HID + n * 64 + d] = ob;
    }
}

// =================================================================
extern "C" void kernel_launch(void* const* d_in, const int* in_sizes, int n_in,
                              void* d_out, int out_size)
{
    const float* hidden = (const float*)d_in[0];
    const float* mask   = (const float*)d_in[1];
    const float* adj    = (const float*)d_in[2];
    const float* Wq     = (const float*)d_in[3];
    const float* bq     = (const float*)d_in[4];
    const float* Wk     = (const float*)d_in[5];
    const float* bk     = (const float*)d_in[6];
    const float* Wv     = (const float*)d_in[7];
    const float* bv     = (const float*)d_in[8];
    const float* bili   = (const float*)d_in[9];
    const float* absb   = (const float*)d_in[10];
    float* out = (float*)d_out;
    (void)in_sizes; (void)n_in; (void)out_size;

    cudaFuncSetAttribute(proj_mma_kernel, cudaFuncAttributeMaxDynamicSharedMemorySize, PJ_SMEM);
    cudaFuncSetAttribute(qb_mma_kernel, cudaFuncAttributeMaxDynamicSharedMemorySize, QB_SMEM);
    cudaFuncSetAttribute(flash_kernel, cudaFuncAttributeMaxDynamicSharedMemorySize, FL_SMEM);

    convx_kernel<<<BB * SQ * HID / 4 / 256, 256>>>(hidden);
    convw_kernel<<<3 * HID * HID / 4 / 256, 256>>>(Wq, Wk, Wv);
    proj_mma_kernel<<<dim3(HID / 64, BB * SQ / 128, 3), 256, PJ_SMEM>>>(bq, bk, bv);
    qb_mma_kernel<<<dim3(SQ / 128, BN, RR), 256, QB_SMEM>>>(bili);
    vt_kernel<<<dim3(SQ / 64, BN), 256>>>();
    pack_kernel<<<dim3(SQ / 32, BB, RR), 256>>>(adj);
    flash_kernel<<<dim3(NH, SQ / 128, BB), 256, FL_SMEM>>>(absb, mask, out);
}

// round 7
// speedup vs baseline: 4.4833x; 1.7603x over previous
#include <cuda_runtime.h>
#include <cuda_bf16.h>
#include <cstdint>
#include <math.h>

#define SQ   2048
#define HID  768
#define BB   2
#define NH   12
#define DH   64
#define RR   5
#define BN   24

// ---------------- device scratch ----------------
__device__ float g_v   [(size_t)BN * SQ * DH];
__device__ __nv_bfloat16 g_xh[(size_t)BB * SQ * HID];
__device__ __nv_bfloat16 g_xl[(size_t)BB * SQ * HID];
__device__ __nv_bfloat16 g_wh[(size_t)3 * HID * HID];
__device__ __nv_bfloat16 g_wl[(size_t)3 * HID * HID];
__device__ __nv_bfloat16 g_qh[(size_t)6 * BN * SQ * DH];   // slot 0..5 hi
__device__ __nv_bfloat16 g_ql[(size_t)BN * SQ * DH];       // slot 0 lo only
__device__ __nv_bfloat16 g_kh[(size_t)BN * SQ * DH];
__device__ __nv_bfloat16 g_kl[(size_t)BN * SQ * DH];
__device__ __nv_bfloat16 g_vth[(size_t)BN * DH * SQ];      // V^T [bn][d][s] hi
__device__ __nv_bfloat16 g_vtl[(size_t)BN * DH * SQ];      // V^T [bn][d][s] lo
__device__ unsigned g_adjbits[(size_t)RR * BB * (SQ / 32) * SQ];

// ================= helpers =================
__device__ __forceinline__ uint32_t smem_to_u32(const void* p) {
    uint32_t a;
    asm("{ .reg .u64 t; cvta.to.shared.u64 t, %1; cvt.u32.u64 %0, t; }" : "=r"(a) : "l"(p));
    return a;
}
__device__ __forceinline__ unsigned pack2(__nv_bfloat16 a, __nv_bfloat16 b) {
    __nv_bfloat162 t; t.x = a; t.y = b;
    return *reinterpret_cast<unsigned*>(&t);
}
__device__ __forceinline__ void ldsm_x4(uint32_t* r, uint32_t addr) {
    asm volatile("ldmatrix.sync.aligned.m8n8.x4.shared.b16 {%0,%1,%2,%3}, [%4];"
        : "=r"(r[0]), "=r"(r[1]), "=r"(r[2]), "=r"(r[3]) : "r"(addr));
}
__device__ __forceinline__ void ldsm_x2(uint32_t* r, uint32_t addr) {
    asm volatile("ldmatrix.sync.aligned.m8n8.x2.shared.b16 {%0,%1}, [%2];"
        : "=r"(r[0]), "=r"(r[1]) : "r"(addr));
}
__device__ __forceinline__ void mma16816(float* d, const uint32_t* a, const uint32_t* b) {
    asm volatile(
        "mma.sync.aligned.m16n8k16.row.col.f32.bf16.bf16.f32 "
        "{%0,%1,%2,%3}, {%4,%5,%6,%7}, {%8,%9}, {%0,%1,%2,%3};"
        : "+f"(d[0]), "+f"(d[1]), "+f"(d[2]), "+f"(d[3])
        : "r"(a[0]), "r"(a[1]), "r"(a[2]), "r"(a[3]), "r"(b[0]), "r"(b[1]));
}
__device__ __forceinline__ unsigned split_hi(float x, float y, float& lx, float& ly) {
    __nv_bfloat16 hx = __float2bfloat16(x), hy = __float2bfloat16(y);
    lx = x - __bfloat162float(hx);
    ly = y - __bfloat162float(hy);
    return pack2(hx, hy);
}
#define SWZ8(row, ch)   (((row) * 128) + ((((ch) ^ ((row) & 7))) << 4))

// ============ conv X -> bf16 hi/lo ============
__global__ __launch_bounds__(256) void convx_kernel(const float* __restrict__ X)
{
    int c = blockIdx.x * 256 + threadIdx.x;
    float4 v = ((const float4*)X)[c];
    float lx, ly, lz, lw;
    uint2 h, l;
    h.x = split_hi(v.x, v.y, lx, ly);
    h.y = split_hi(v.z, v.w, lz, lw);
    l.x = pack2(__float2bfloat16(lx), __float2bfloat16(ly));
    l.y = pack2(__float2bfloat16(lz), __float2bfloat16(lw));
    ((uint2*)g_xh)[c] = h;
    ((uint2*)g_xl)[c] = l;
}

// ============ conv W (q,k,v) -> bf16 hi/lo ============
__global__ __launch_bounds__(256) void convw_kernel(
    const float* __restrict__ Wq, const float* __restrict__ Wk, const float* __restrict__ Wv)
{
    const int per = HID * HID / 4;
    int c = blockIdx.x * 256 + threadIdx.x;
    int z = c / per;
    const float* W = (z == 0) ? Wq : (z == 1) ? Wk : Wv;
    float4 v = ((const float4*)W)[c - z * per];
    float lx, ly, lz, lw;
    uint2 h, l;
    h.x = split_hi(v.x, v.y, lx, ly);
    h.y = split_hi(v.z, v.w, lz, lw);
    l.x = pack2(__float2bfloat16(lx), __float2bfloat16(ly));
    l.y = pack2(__float2bfloat16(lz), __float2bfloat16(lw));
    ((uint2*)g_wh)[c] = h;
    ((uint2*)g_wl)[c] = l;
}

// ============ proj via HMMA: out = X @ W^T + b ============
#define PJ_XH 0
#define PJ_XL 16384
#define PJ_WH 32768
#define PJ_WL 40960
#define PJ_SMEM 49152

__global__ __launch_bounds__(256) void proj_mma_kernel(
    const float* __restrict__ bq, const float* __restrict__ bk, const float* __restrict__ bv)
{
    extern __shared__ char smem[];
    const uint32_t sbase = smem_to_u32(smem);
    const int otile = blockIdx.x, mtile = blockIdx.y, z = blockIdx.z;
    const float* bias = (z == 0) ? bq : (z == 1) ? bk : bv;
    const int tid = threadIdx.x, wid = tid >> 5, lane = tid & 31;
    const int m0 = wid * 16;
    const int rowA = m0 + (lane & 15);
    const int selA = lane >> 4;
    const int rowB8 = lane & 7;
    const int selB = (lane >> 3) & 1;
    const int c2 = 2 * (lane & 3);

    float fin[32];
#pragma unroll
    for (int e = 0; e < 32; e++) fin[e] = 0.f;

    for (int kc = 0; kc < HID / 64; kc++) {
        __syncthreads();
#pragma unroll
        for (int c = 0; c < 8; c++) {
            int idx = tid + 256 * c;
            int half = idx >> 10;
            int rem = idx & 1023;
            int row = rem >> 3, ch = rem & 7;
            const __nv_bfloat16* src = (half ? g_xl : g_xh) +
                (size_t)(mtile * 128 + row) * HID + kc * 64 + ch * 8;
            *(uint4*)(smem + (half ? PJ_XL : PJ_XH) + SWZ8(row, ch)) = *(const uint4*)src;
        }
#pragma unroll
        for (int c = 0; c < 4; c++) {
            int idx = tid + 256 * c;
            int half = idx >> 9;
            int rem = idx & 511;
            int row = rem >> 3, ch = rem & 7;
            const __nv_bfloat16* src = (half ? g_wl : g_wh) +
                ((size_t)z * HID + otile * 64 + row) * HID + kc * 64 + ch * 8;
            *(uint4*)(smem + (half ? PJ_WL : PJ_WH) + SWZ8(row, ch)) = *(const uint4*)src;
        }
        __syncthreads();

#pragma unroll
        for (int ks = 0; ks < 4; ks++) {
            uint32_t Ah[4], Al[4];
            ldsm_x4(Ah, sbase + PJ_XH + SWZ8(rowA, ks * 2 + selA));
            ldsm_x4(Al, sbase + PJ_XL + SWZ8(rowA, ks * 2 + selA));
#pragma unroll
            for (int nf = 0; nf < 8; nf++) {
                uint32_t Bh[2], Bl[2];
                ldsm_x2(Bh, sbase + PJ_WH + SWZ8(nf * 8 + rowB8, ks * 2 + selB));
                ldsm_x2(Bl, sbase + PJ_WL + SWZ8(nf * 8 + rowB8, ks * 2 + selB));
                mma16816(fin + nf * 4, Ah, Bh);
                mma16816(fin + nf * 4, Ah, Bl);
                mma16816(fin + nf * 4, Al, Bh);
            }
        }
    }

    const int ma = mtile * 128 + m0 + (lane >> 2);
    const int b = ma >> 11;
    const int sa = ma & (SQ - 1), sb = sa + 8;
    const int bn = b * NH + otile;
#pragma unroll
    for (int nf = 0; nf < 8; nf++) {
        int col = nf * 8 + c2;
        float bsx = bias[otile * 64 + col], bsy = bias[otile * 64 + col + 1];
        float a0 = fin[nf * 4 + 0] + bsx, a1 = fin[nf * 4 + 1] + bsy;
        float b0 = fin[nf * 4 + 2] + bsx, b1 = fin[nf * 4 + 3] + bsy;
        size_t offa = ((size_t)bn * SQ + sa) * DH + col;
        size_t offb = ((size_t)bn * SQ + sb) * DH + col;
        if (z == 2) {
            *(float2*)&g_v[offa] = make_float2(a0, a1);
            *(float2*)&g_v[offb] = make_float2(b0, b1);
        } else {
            __nv_bfloat16* dh = (z == 0) ? g_qh : g_kh;
            __nv_bfloat16* dl = (z == 0) ? g_ql : g_kl;
            float l0, l1;
            unsigned h;
            h = split_hi(a0, a1, l0, l1);
            *(unsigned*)&dh[offa] = h;
            *(unsigned*)&dl[offa] = pack2(__float2bfloat16(l0), __float2bfloat16(l1));
            h = split_hi(b0, b1, l0, l1);
            *(unsigned*)&dh[offb] = h;
            *(unsigned*)&dl[offb] = pack2(__float2bfloat16(l0), __float2bfloat16(l1));
        }
    }
}

// ============ qb via HMMA: q'_r = q @ bili[r,n] -> slot 1+r (hi only) ============
#define QB_QH 0
#define QB_QL 16384
#define QB_BH 32768
#define QB_BL 40960
#define QB_SMEM 49152

__global__ __launch_bounds__(256) void qb_mma_kernel(const float* __restrict__ bili)
{
    extern __shared__ char smem[];
    const uint32_t sbase = smem_to_u32(smem);
    const int it = blockIdx.x, bn = blockIdx.y, r = blockIdx.z;
    const int n = bn % NH;
    const int tid = threadIdx.x, wid = tid >> 5, lane = tid & 31;
    const int m0 = wid * 16;
    const int rowA = m0 + (lane & 15);
    const int selA = lane >> 4;
    const int rowB8 = lane & 7;
    const int selB = (lane >> 3) & 1;
    const int c2 = 2 * (lane & 3);

#pragma unroll
    for (int c = 0; c < 8; c++) {
        int idx = tid + 256 * c;
        int half = idx >> 10;
        int rem = idx & 1023;
        int row = rem >> 3, ch = rem & 7;
        const __nv_bfloat16* src = (half ? g_ql : g_qh) +
            ((size_t)bn * SQ + it * 128 + row) * DH + ch * 8;
        *(uint4*)(smem + (half ? QB_QL : QB_QH) + SWZ8(row, ch)) = *(const uint4*)src;
    }
    const float* bb = bili + ((size_t)r * NH + n) * DH * DH;
#pragma unroll
    for (int c = 0; c < 16; c++) {
        int id = tid + 256 * c;
        int p = id >> 6, t = id & 63;
        float v = bb[p * 64 + t];
        __nv_bfloat16 hv = __float2bfloat16(v);
        float lo = v - __bfloat162float(hv);
        uint32_t byteoff = SWZ8(t, p >> 3) + (p & 7) * 2;
        *(__nv_bfloat16*)(smem + QB_BH + byteoff) = hv;
        *(__nv_bfloat16*)(smem + QB_BL + byteoff) = __float2bfloat16(lo);
    }
    __syncthreads();

    float fin[32];
#pragma unroll
    for (int e = 0; e < 32; e++) fin[e] = 0.f;

#pragma unroll
    for (int ks = 0; ks < 4; ks++) {
        uint32_t Ah[4], Al[4];
        ldsm_x4(Ah, sbase + QB_QH + SWZ8(rowA, ks * 2 + selA));
        ldsm_x4(Al, sbase + QB_QL + SWZ8(rowA, ks * 2 + selA));
#pragma unroll
        for (int nf = 0; nf < 8; nf++) {
            uint32_t Bh[2], Bl[2];
            ldsm_x2(Bh, sbase + QB_BH + SWZ8(nf * 8 + rowB8, ks * 2 + selB));
            ldsm_x2(Bl, sbase + QB_BL + SWZ8(nf * 8 + rowB8, ks * 2 + selB));
            mma16816(fin + nf * 4, Ah, Bh);
            mma16816(fin + nf * 4, Ah, Bl);
            mma16816(fin + nf * 4, Al, Bh);
        }
    }

    const int slot = 1 + r;
    const int ia = it * 128 + m0 + (lane >> 2);
    const int ib = ia + 8;
#pragma unroll
    for (int nf = 0; nf < 8; nf++) {
        int col = nf * 8 + c2;
        size_t offa = (((size_t)slot * BN + bn) * SQ + ia) * DH + col;
        size_t offb = (((size_t)slot * BN + bn) * SQ + ib) * DH + col;
        *(unsigned*)&g_qh[offa] = pack2(__float2bfloat16(fin[nf * 4 + 0]), __float2bfloat16(fin[nf * 4 + 1]));
        *(unsigned*)&g_qh[offb] = pack2(__float2bfloat16(fin[nf * 4 + 2]), __float2bfloat16(fin[nf * 4 + 3]));
    }
}

// ============ transpose+convert V -> g_vth/g_vtl [bn][d][s] ============
__global__ __launch_bounds__(256) void vt_kernel()
{
    const int st = blockIdx.x, bn = blockIdx.y;
    __shared__ float tile[64][65];
    const int t = threadIdx.x;
#pragma unroll
    for (int c = 0; c < 4; c++) {
        int id = t + 256 * c, row = id >> 4, c4 = (id & 15) << 2;
        float4 v = *(const float4*)&g_v[((size_t)bn * SQ + st * 64 + row) * DH + c4];
        tile[row][c4 + 0] = v.x; tile[row][c4 + 1] = v.y;
        tile[row][c4 + 2] = v.z; tile[row][c4 + 3] = v.w;
    }
    __syncthreads();
#pragma unroll
    for (int c = 0; c < 4; c++) {
        int id = t + 256 * c, d = id >> 4, s4 = (id & 15) << 2;
        float f0 = tile[s4 + 0][d], f1 = tile[s4 + 1][d];
        float f2 = tile[s4 + 2][d], f3 = tile[s4 + 3][d];
        float l0, l1, l2, l3;
        uint2 hv, lv;
        hv.x = split_hi(f0, f1, l0, l1);
        hv.y = split_hi(f2, f3, l2, l3);
        lv.x = pack2(__float2bfloat16(l0), __float2bfloat16(l1));
        lv.y = pack2(__float2bfloat16(l2), __float2bfloat16(l3));
        size_t off = ((size_t)bn * DH + d) * SQ + st * 64 + s4;
        *(uint2*)&g_vth[off] = hv;
        *(uint2*)&g_vtl[off] = lv;
    }
}

// ============ pack adj -> bitmask [r][b][jword][i] ============
__global__ __launch_bounds__(256) void pack_kernel(const float* __restrict__ adj)
{
    const int jw = blockIdx.x, b = blockIdx.y, r = blockIdx.z;
#pragma unroll
    for (int ii = 0; ii < 8; ii++) {
        int i = threadIdx.x + 256 * ii;
        const float* src = adj + (((size_t)(r * BB + b)) * SQ + i) * SQ + jw * 32;
        unsigned bits = 0;
#pragma unroll
        for (int e8 = 0; e8 < 8; e8++) {
            float4 v = *(const float4*)(src + e8 * 4);
            bits |= (unsigned)(v.x != 0.f) << (e8 * 4 + 0);
            bits |= (unsigned)(v.y != 0.f) << (e8 * 4 + 1);
            bits |= (unsigned)(v.z != 0.f) << (e8 * 4 + 2);
            bits |= (unsigned)(v.w != 0.f) << (e8 * 4 + 3);
        }
        g_adjbits[((size_t)(r * BB + b) * 64 + jw) * SQ + i] = bits;
    }
}

// ============ fused flash (score + softmax + ctx) ============
// grid (NH, SQ/64, BB), block 128 (4 warps x 16 rows). 2 CTAs/SM.
// SMEM: slot0 hi/lo + slot1..5 hi (7 x 8KB), K hi/lo (2 x 8KB), Vt hi/lo (2 x 8KB) = 88KB
#define FQ0H 0
#define FQ0L 8192
#define FQS(s)    (((s) + 1) * 8192)        // s in 1..5
#define FKT(half) (57344 + (half) * 8192)
#define FVT(half) (73728 + (half) * 8192)
#define FL_SMEM   90112

__global__ __launch_bounds__(128) void flash_kernel(
    const float* __restrict__ absb, const float* __restrict__ mask,
    float* __restrict__ out)
{
    extern __shared__ char smem[];
    const uint32_t sbase = smem_to_u32(smem);
    const int n = blockIdx.x, it = blockIdx.y, b = blockIdx.z;
    const int bn = b * NH + n;
    const int i0 = it * 64;
    const int tid = threadIdx.x, wid = tid >> 5, lane = tid & 31;
    const int m0 = wid * 16;

    // ---- load 7 Q tiles (64x64 bf16, swizzled): slot0 h+l, slots1-5 hi ----
#pragma unroll
    for (int c = 0; c < 28; c++) {
        int idx = tid + 128 * c;
        int tile = idx >> 9;                // 0..6
        int rem = idx & 511;
        int row = rem >> 3, ch = rem & 7;
        int slot = (tile <= 1) ? 0 : (tile - 1);
        const __nv_bfloat16* base = (tile == 1) ? g_ql : g_qh;
        const __nv_bfloat16* src = base +
            (((size_t)slot * BN + bn) * SQ + i0 + row) * DH + ch * 8;
        *(uint4*)(smem + tile * 8192 + SWZ8(row, ch)) = *(const uint4*)src;
    }

    float ab[RR];
#pragma unroll
    for (int r = 0; r < RR; r++) ab[r] = absb[r * NH + n];

    const int rowA = m0 + (lane & 15);
    const int selA = lane >> 4;
    const int rowB8 = lane & 7;
    const int selB = (lane >> 3) & 1;
    const int c2 = 2 * (lane & 3);
    const int ia = i0 + m0 + (lane >> 2);
    const int ib = ia + 8;

    float O[32];
#pragma unroll
    for (int e = 0; e < 32; e++) O[e] = 0.f;
    float mr[2] = {-1e30f, -1e30f};
    float lr[2] = {0.f, 0.f};

    for (int jt = 0; jt < 32; jt++) {
        __syncthreads();
        // ---- load K hi/lo (64x64) and Vt hi/lo (64d x 64j) ----
#pragma unroll
        for (int c = 0; c < 16; c++) {
            int idx = tid + 128 * c;
            int seg = idx >> 9;             // 0:kh 1:kl 2:vh 3:vl
            int rem = idx & 511;
            int row = rem >> 3, ch = rem & 7;
            const __nv_bfloat16* src;
            uint32_t dstoff;
            if (seg < 2) {
                src = (seg ? g_kl : g_kh) + ((size_t)bn * SQ + jt * 64 + row) * DH + ch * 8;
                dstoff = FKT(seg);
            } else {
                src = ((seg == 3) ? g_vtl : g_vth) + ((size_t)bn * DH + row) * SQ + jt * 64 + ch * 8;
                dstoff = FVT(seg - 2);
            }
            *(uint4*)(smem + dstoff + SWZ8(row, ch)) = *(const uint4*)src;
        }
        __syncthreads();

#pragma unroll
        for (int jh = 0; jh < 2; jh++) {
            uint32_t BK[2][4][4][2];
#pragma unroll
            for (int h = 0; h < 2; h++)
#pragma unroll
                for (int ks = 0; ks < 4; ks++)
#pragma unroll
                    for (int nf = 0; nf < 4; nf++)
                        ldsm_x2(BK[h][ks][nf],
                                sbase + FKT(h) + SWZ8(jh * 32 + nf * 8 + rowB8, ks * 2 + selB));

            const int jw = jt * 2 + jh;
            unsigned aw1[RR], aw2[RR];
#pragma unroll
            for (int r = 0; r < RR; r++) {
                aw1[r] = g_adjbits[((size_t)(r * BB + b) * 64 + jw) * SQ + ia];
                aw2[r] = g_adjbits[((size_t)(r * BB + b) * 64 + jw) * SQ + ib];
            }

            // slot 0: hi/lo 3-pass
            float fin[16] = {};
#pragma unroll
            for (int ks = 0; ks < 4; ks++) {
                uint32_t Ah[4], Al[4];
                ldsm_x4(Ah, sbase + FQ0H + SWZ8(rowA, ks * 2 + selA));
                ldsm_x4(Al, sbase + FQ0L + SWZ8(rowA, ks * 2 + selA));
#pragma unroll
                for (int nf = 0; nf < 4; nf++) {
                    mma16816(fin + nf * 4, Ah, BK[0][ks][nf]);
                    mma16816(fin + nf * 4, Ah, BK[1][ks][nf]);
                    mma16816(fin + nf * 4, Al, BK[0][ks][nf]);
                }
            }

            // slots 1..5: hi-only 1-pass
#pragma unroll
            for (int s = 1; s < 6; s++) {
                float tmp[16] = {};
#pragma unroll
                for (int ks = 0; ks < 4; ks++) {
                    uint32_t Ah[4];
                    ldsm_x4(Ah, sbase + FQS(s) + SWZ8(rowA, ks * 2 + selA));
#pragma unroll
                    for (int nf = 0; nf < 4; nf++)
                        mma16816(tmp + nf * 4, Ah, BK[0][ks][nf]);
                }
                const int r = s - 1;
                const float abr = ab[r];
#pragma unroll
                for (int nf = 0; nf < 4; nf++) {
                    int sh = nf * 8 + c2;
                    if ((aw1[r] >> sh) & 1)       fin[nf * 4 + 0] += tmp[nf * 4 + 0] + abr;
                    if ((aw1[r] >> (sh + 1)) & 1) fin[nf * 4 + 1] += tmp[nf * 4 + 1] + abr;
                    if ((aw2[r] >> sh) & 1)       fin[nf * 4 + 2] += tmp[nf * 4 + 2] + abr;
                    if ((aw2[r] >> (sh + 1)) & 1) fin[nf * 4 + 3] += tmp[nf * 4 + 3] + abr;
                }
            }

#pragma unroll
            for (int nf = 0; nf < 4; nf++) {
                float2 mk = __ldg((const float2*)&mask[b * SQ + jt * 64 + jh * 32 + nf * 8 + c2]);
                fin[nf * 4 + 0] = fin[nf * 4 + 0] * 0.125f + mk.x;
                fin[nf * 4 + 1] = fin[nf * 4 + 1] * 0.125f + mk.y;
                fin[nf * 4 + 2] = fin[nf * 4 + 2] * 0.125f + mk.x;
                fin[nf * 4 + 3] = fin[nf * 4 + 3] * 0.125f + mk.y;
            }

            float mxa = -1e30f, mxb = -1e30f;
#pragma unroll
            for (int nf = 0; nf < 4; nf++) {
                mxa = fmaxf(mxa, fmaxf(fin[nf * 4 + 0], fin[nf * 4 + 1]));
                mxb = fmaxf(mxb, fmaxf(fin[nf * 4 + 2], fin[nf * 4 + 3]));
            }
            mxa = fmaxf(mxa, __shfl_xor_sync(0xffffffffu, mxa, 1));
            mxa = fmaxf(mxa, __shfl_xor_sync(0xffffffffu, mxa, 2));
            mxb = fmaxf(mxb, __shfl_xor_sync(0xffffffffu, mxb, 1));
            mxb = fmaxf(mxb, __shfl_xor_sync(0xffffffffu, mxb, 2));
            float mna = fmaxf(mr[0], mxa), mnb = fmaxf(mr[1], mxb);
            float ala = __expf(mr[0] - mna), alb = __expf(mr[1] - mnb);
            mr[0] = mna; mr[1] = mnb;

            float sa = 0.f, sb = 0.f;
#pragma unroll
            for (int nf = 0; nf < 4; nf++) {
                fin[nf * 4 + 0] = __expf(fin[nf * 4 + 0] - mna);
                fin[nf * 4 + 1] = __expf(fin[nf * 4 + 1] - mna);
                fin[nf * 4 + 2] = __expf(fin[nf * 4 + 2] - mnb);
                fin[nf * 4 + 3] = __expf(fin[nf * 4 + 3] - mnb);
                sa += fin[nf * 4 + 0] + fin[nf * 4 + 1];
                sb += fin[nf * 4 + 2] + fin[nf * 4 + 3];
            }
            sa += __shfl_xor_sync(0xffffffffu, sa, 1);
            sa += __shfl_xor_sync(0xffffffffu, sa, 2);
            sb += __shfl_xor_sync(0xffffffffu, sb, 1);
            sb += __shfl_xor_sync(0xffffffffu, sb, 2);
            lr[0] = lr[0] * ala + sa;
            lr[1] = lr[1] * alb + sb;

#pragma unroll
            for (int dn = 0; dn < 8; dn++) {
                O[dn * 4 + 0] *= ala; O[dn * 4 + 1] *= ala;
                O[dn * 4 + 2] *= alb; O[dn * 4 + 3] *= alb;
            }

            uint32_t Ph[2][4], Pl[2][4];
#pragma unroll
            for (int jk = 0; jk < 2; jk++) {
                float l0, l1;
                Ph[jk][0] = split_hi(fin[(2 * jk) * 4 + 0], fin[(2 * jk) * 4 + 1], l0, l1);
                Pl[jk][0] = pack2(__float2bfloat16(l0), __float2bfloat16(l1));
                Ph[jk][1] = split_hi(fin[(2 * jk) * 4 + 2], fin[(2 * jk) * 4 + 3], l0, l1);
                Pl[jk][1] = pack2(__float2bfloat16(l0), __float2bfloat16(l1));
                Ph[jk][2] = split_hi(fin[(2 * jk + 1) * 4 + 0], fin[(2 * jk + 1) * 4 + 1], l0, l1);
                Pl[jk][2] = pack2(__float2bfloat16(l0), __float2bfloat16(l1));
                Ph[jk][3] = split_hi(fin[(2 * jk + 1) * 4 + 2], fin[(2 * jk + 1) * 4 + 3], l0, l1);
                Pl[jk][3] = pack2(__float2bfloat16(l0), __float2bfloat16(l1));
            }

#pragma unroll
            for (int jk = 0; jk < 2; jk++) {
#pragma unroll
                for (int dn = 0; dn < 8; dn++) {
                    uint32_t BVh[2], BVl[2];
                    ldsm_x2(BVh, sbase + FVT(0) + SWZ8(dn * 8 + rowB8, jh * 4 + jk * 2 + selB));
                    ldsm_x2(BVl, sbase + FVT(1) + SWZ8(dn * 8 + rowB8, jh * 4 + jk * 2 + selB));
                    mma16816(O + dn * 4, Ph[jk], BVh);
                    mma16816(O + dn * 4, Ph[jk], BVl);
                    mma16816(O + dn * 4, Pl[jk], BVh);
                }
            }
        }
    }

    const float inva = 1.0f / lr[0], invb = 1.0f / lr[1];
#pragma unroll
    for (int dn = 0; dn < 8; dn++) {
        int d = dn * 8 + c2;
        float2 oa, ob;
        oa.x = O[dn * 4 + 0] * inva; oa.y = O[dn * 4 + 1] * inva;
        ob.x = O[dn * 4 + 2] * invb; ob.y = O[dn * 4 + 3] * invb;
        *(float2*)&out[((size_t)b * SQ + ia) * HID + n * 64 + d] = oa;
        *(float2*)&out[((size_t)b * SQ + ib) * HID + n * 64 + d] = ob;
    }
}

// =================================================================
extern "C" void kernel_launch(void* const* d_in, const int* in_sizes, int n_in,
                              void* d_out, int out_size)
{
    const float* hidden = (const float*)d_in[0];
    const float* mask   = (const float*)d_in[1];
    const float* adj    = (const float*)d_in[2];
    const float* Wq     = (const float*)d_in[3];
    const float* bq     = (const float*)d_in[4];
    const float* Wk     = (const float*)d_in[5];
    const float* bk     = (const float*)d_in[6];
    const float* Wv     = (const float*)d_in[7];
    const float* bv     = (const float*)d_in[8];
    const float* bili   = (const float*)d_in[9];
    const float* absb   = (const float*)d_in[10];
    float* out = (float*)d_out;
    (void)in_sizes; (void)n_in; (void)out_size;

    cudaFuncSetAttribute(proj_mma_kernel, cudaFuncAttributeMaxDynamicSharedMemorySize, PJ_SMEM);
    cudaFuncSetAttribute(qb_mma_kernel, cudaFuncAttributeMaxDynamicSharedMemorySize, QB_SMEM);
    cudaFuncSetAttribute(flash_kernel, cudaFuncAttributeMaxDynamicSharedMemorySize, FL_SMEM);

    convx_kernel<<<BB * SQ * HID / 4 / 256, 256>>>(hidden);
    convw_kernel<<<3 * HID * HID / 4 / 256, 256>>>(Wq, Wk, Wv);
    proj_mma_kernel<<<dim3(HID / 64, BB * SQ / 128, 3), 256, PJ_SMEM>>>(bq, bk, bv);
    qb_mma_kernel<<<dim3(SQ / 128, BN, RR), 256, QB_SMEM>>>(bili);
    vt_kernel<<<dim3(SQ / 64, BN), 256>>>();
    pack_kernel<<<dim3(SQ / 32, BB, RR), 256>>>(adj);
    flash_kernel<<<dim3(NH, SQ / 64, BB), 128, FL_SMEM>>>(absb, mask, out);
}